// round 5
// baseline (speedup 1.0000x reference)
#include <cuda_runtime.h>
#include <cuda_bf16.h>
#include <cstdint>

// Problem constants
#define BB   4
#define TT   512
#define KK   63
#define DD   384
#define DFF  1536
#define MM   (BB*TT)          // 2048
#define NOUT 96
#define FREQ 1016

// ---------------------------------------------------------------------------
// Scratch (device globals; ONLY referenced from device code — see R3 bug).
// ---------------------------------------------------------------------------
__device__ __align__(16) __nv_bfloat16 g_An_hi[(size_t)KK * MM * DD];
__device__ __align__(16) __nv_bfloat16 g_An_lo[(size_t)KK * MM * DD];
__device__ __align__(16) __nv_bfloat16 g_W0T_hi[(size_t)KK * DFF * DD];
__device__ __align__(16) __nv_bfloat16 g_W0T_lo[(size_t)KK * DFF * DD];
__device__ __align__(16) __nv_bfloat16 g_W1T_hi[(size_t)KK * NOUT * DFF];
__device__ __align__(16) __nv_bfloat16 g_W1T_lo[(size_t)KK * NOUT * DFF];
__device__ __align__(16) __nv_bfloat16 g_H1h[(size_t)KK * MM * DFF];
__device__ __align__(16) __nv_bfloat16 g_H1l[(size_t)KK * MM * DFF];

// ---------------------------------------------------------------------------
// Portable PTX helpers (plain sm_103)
// ---------------------------------------------------------------------------
__device__ __forceinline__ uint32_t smem_u32(const void* p) {
    uint32_t a;
    asm("{ .reg .u64 t; cvta.to.shared.u64 t, %1; cvt.u32.u64 %0, t; }"
        : "=r"(a) : "l"(p));
    return a;
}
#define CP16(dst, src) \
    asm volatile("cp.async.cg.shared.global [%0], [%1], 16;" \
                 :: "r"(dst), "l"(src) : "memory")
#define CP_COMMIT() asm volatile("cp.async.commit_group;" ::: "memory")
#define CP_WAIT1()  asm volatile("cp.async.wait_group 1;"  ::: "memory")
#define CP_WAIT0()  asm volatile("cp.async.wait_group 0;"  ::: "memory")

__device__ __forceinline__ void ldsm4(uint32_t r[4], uint32_t addr) {
    asm volatile("ldmatrix.sync.aligned.m8n8.x4.shared.b16 {%0,%1,%2,%3}, [%4];"
        : "=r"(r[0]), "=r"(r[1]), "=r"(r[2]), "=r"(r[3]) : "r"(addr));
}
__device__ __forceinline__ void mma_bf16(float c[4], const uint32_t a[4],
                                         uint32_t b0, uint32_t b1) {
    asm volatile(
        "mma.sync.aligned.m16n8k16.row.col.f32.bf16.bf16.f32 "
        "{%0,%1,%2,%3}, {%4,%5,%6,%7}, {%8,%9}, {%0,%1,%2,%3};"
        : "+f"(c[0]), "+f"(c[1]), "+f"(c[2]), "+f"(c[3])
        : "r"(a[0]), "r"(a[1]), "r"(a[2]), "r"(a[3]), "r"(b0), "r"(b1));
}

// Swizzled byte offset inside a [rows x 32] bf16 tile packed as 128B lines.
// KEY property: tswz(r, c) == tswz(r, 0) ^ (c << 4)  (c = 16B chunk 0..3)
__device__ __forceinline__ uint32_t tswz(int r, int c) {
    uint32_t line = (uint32_t)r >> 1;
    uint32_t pos  = ((((uint32_t)r & 1u) << 2) | (uint32_t)c) ^ (line & 7u);
    return line * 128u + pos * 16u;
}

__device__ __forceinline__ void split2(float a, float b, uint32_t& hi, uint32_t& lo) {
    __nv_bfloat16 ha = __float2bfloat16(a), hb = __float2bfloat16(b);
    float ra = a - __bfloat162float(ha);
    float rb = b - __bfloat162float(hb);
    __nv_bfloat162 H; H.x = ha; H.y = hb;
    __nv_bfloat162 L = __floats2bfloat162_rn(ra, rb);
    hi = *reinterpret_cast<uint32_t*>(&H);
    lo = *reinterpret_cast<uint32_t*>(&L);
}

// ---------------------------------------------------------------------------
// RMSNorm + gamma + bf16 hi/lo split.  x[m][k][d] -> An[k][m][d]
// ---------------------------------------------------------------------------
__global__ __launch_bounds__(256) void rms_split_kernel(
    const float* __restrict__ x, const float* __restrict__ gamma)
{
    int gt = blockIdx.x * blockDim.x + threadIdx.x;
    int row = gt >> 5, lane = gt & 31;
    if (row >= MM * KK) return;
    int m = row / KK, k = row - m * KK;

    const float* xr = x + (size_t)row * DD;
    float4 v[3];
    float s = 0.f;
    #pragma unroll
    for (int i = 0; i < 3; i++) {
        v[i] = *reinterpret_cast<const float4*>(&xr[(lane + i * 32) * 4]);
        s += v[i].x*v[i].x + v[i].y*v[i].y + v[i].z*v[i].z + v[i].w*v[i].w;
    }
    #pragma unroll
    for (int o = 16; o > 0; o >>= 1) s += __shfl_xor_sync(0xffffffffu, s, o);
    s = rsqrtf(s * (1.0f / DD) + 1e-8f);

    const float* gk = gamma + k * DD;
    __nv_bfloat16* oh = g_An_hi + ((size_t)k * MM + m) * DD;
    __nv_bfloat16* ol = g_An_lo + ((size_t)k * MM + m) * DD;
    #pragma unroll
    for (int i = 0; i < 3; i++) {
        int d = (lane + i * 32) * 4;
        float4 g = *reinterpret_cast<const float4*>(&gk[d]);
        float a0 = v[i].x*s*g.x, a1 = v[i].y*s*g.y, a2 = v[i].z*s*g.z, a3 = v[i].w*s*g.w;
        uint2 H, L;
        split2(a0, a1, H.x, L.x);
        split2(a2, a3, H.y, L.y);
        *reinterpret_cast<uint2*>(oh + d) = H;
        *reinterpret_cast<uint2*>(ol + d) = L;
    }
}

// ---------------------------------------------------------------------------
// Per-band transpose + bf16 hi/lo split (device-resolved destinations)
// ---------------------------------------------------------------------------
template <int SEL>
__global__ __launch_bounds__(256) void transpose_split_kernel(
    const float* __restrict__ in, int R, int C)
{
    __nv_bfloat16* __restrict__ oh = (SEL == 0) ? g_W0T_hi : g_W1T_hi;
    __nv_bfloat16* __restrict__ ol = (SEL == 0) ? g_W0T_lo : g_W1T_lo;

    __shared__ float tile[32][33];
    const float* inp = in + (size_t)blockIdx.z * R * C;
    size_t obase = (size_t)blockIdx.z * C * R;
    int r0 = blockIdx.y * 32, c0 = blockIdx.x * 32;
    int tx = threadIdx.x, ty = threadIdx.y;

    #pragma unroll
    for (int j = 0; j < 4; j++)
        tile[ty + 8*j][tx] = inp[(size_t)(r0 + ty + 8*j) * C + c0 + tx];
    __syncthreads();
    #pragma unroll
    for (int j = 0; j < 4; j++) {
        int oc = c0 + ty + 8*j;
        float val = tile[tx][ty + 8*j];
        __nv_bfloat16 h = __float2bfloat16(val);
        float r = val - __bfloat162float(h);
        oh[obase + (size_t)oc * R + r0 + tx] = h;
        ol[obase + (size_t)oc * R + r0 + tx] = __float2bfloat16(r);
    }
}

// ---------------------------------------------------------------------------
// GEMM1 (mma.sync bf16, 3-term): H1[k] = tanh(An[k] @ W0T[k]^T + b0[k])
//   Block 128x128, K-step 32 (12 iters), cp.async double buffer.
//   8 warps as 2(M)x4(N): warp tile 64x32. In-loop ldmatrix address = base^kx.
// ---------------------------------------------------------------------------
#define G1_STAGE 32768
#define G1_SMEM  (2*G1_STAGE)

__global__ __launch_bounds__(256, 2) void gemm1_mma(const float* __restrict__ b0)
{
    extern __shared__ char smem[];
    const uint32_t sb = smem_u32(smem);
    const int t = threadIdx.x, wid = t >> 5, lane = t & 31;
    const int k = blockIdx.z, mb = blockIdx.y * 128, nb = blockIdx.x * 128;
    const int wm = wid & 1, wn = wid >> 1;

    const __nv_bfloat16* gA0 = g_An_hi  + ((size_t)k * MM  + mb) * DD;
    const __nv_bfloat16* gA1 = g_An_lo  + ((size_t)k * MM  + mb) * DD;
    const __nv_bfloat16* gB0 = g_W0T_hi + ((size_t)k * DFF + nb) * DD;
    const __nv_bfloat16* gB1 = g_W0T_lo + ((size_t)k * DFF + nb) * DD;

    const __nv_bfloat16* gbase[8];
    uint32_t sdst[8];
    #pragma unroll
    for (int j = 0; j < 8; j++) {
        int id = t + j * 256;
        int mat = id >> 9, r = (id >> 2) & 127, c = id & 3;
        const __nv_bfloat16* g =
            (mat == 0) ? gA0 : (mat == 1) ? gA1 : (mat == 2) ? gB0 : gB1;
        gbase[j] = g + (size_t)r * DD + c * 8;
        sdst[j]  = (uint32_t)(mat * 8192) + tswz(r, c);
    }

    // precomputed ldmatrix base offsets (cc folded: base ^ (kc<<5) in-loop)
    const uint32_t laneXor = (uint32_t)((lane >> 4) << 4);
    uint32_t aHiO[4], aLoO[4], bHiO[2], bLoO[2];
    #pragma unroll
    for (int mf = 0; mf < 4; mf++) {
        uint32_t o = tswz(wm * 64 + mf * 16 + (lane & 15), 0) ^ laneXor;
        aHiO[mf] = o; aLoO[mf] = o + 8192;
    }
    #pragma unroll
    for (int g = 0; g < 2; g++) {
        uint32_t o = tswz(wn * 32 + g * 16 + (lane & 15), 0) ^ laneXor;
        bHiO[g] = o + 16384; bLoO[g] = o + 24576;
    }

    float acc[4][4][4];
    #pragma unroll
    for (int a = 0; a < 4; a++)
        #pragma unroll
        for (int b = 0; b < 4; b++)
            #pragma unroll
            for (int c = 0; c < 4; c++) acc[a][b][c] = 0.f;

    #pragma unroll
    for (int j = 0; j < 8; j++) CP16(sb + sdst[j], gbase[j]);
    CP_COMMIT();

    #pragma unroll 1
    for (int it2 = 0; it2 < 6; ++it2) {
        #pragma unroll
        for (int half = 0; half < 2; half++) {
            const int it = it2 * 2 + half;
            const uint32_t stb = sb + (uint32_t)(half * G1_STAGE);
            if (it + 1 < 12) {
                const uint32_t stn = sb + (uint32_t)((half ^ 1) * G1_STAGE);
                const int k0 = (it + 1) * 32;
                #pragma unroll
                for (int j = 0; j < 8; j++) CP16(stn + sdst[j], gbase[j] + k0);
                CP_COMMIT();
                CP_WAIT1();
            } else {
                CP_WAIT0();
            }
            __syncthreads();

            #pragma unroll
            for (int kc = 0; kc < 2; kc++) {
                const uint32_t kx = (uint32_t)(kc << 5);
                uint32_t ah[4][4], al[4][4], bh[2][4], bl[2][4];
                #pragma unroll
                for (int mf = 0; mf < 4; mf++) {
                    ldsm4(ah[mf], stb + (aHiO[mf] ^ kx));
                    ldsm4(al[mf], stb + (aLoO[mf] ^ kx));
                }
                #pragma unroll
                for (int g = 0; g < 2; g++) {
                    ldsm4(bh[g], stb + (bHiO[g] ^ kx));
                    ldsm4(bl[g], stb + (bLoO[g] ^ kx));
                }
                #pragma unroll
                for (int mf = 0; mf < 4; mf++)
                    #pragma unroll
                    for (int nf = 0; nf < 4; nf++) {
                        int g = nf >> 1, s = nf & 1;
                        mma_bf16(acc[mf][nf], ah[mf], bh[g][s], bh[g][s + 2]);
                        mma_bf16(acc[mf][nf], ah[mf], bl[g][s], bl[g][s + 2]);
                        mma_bf16(acc[mf][nf], al[mf], bh[g][s], bh[g][s + 2]);
                    }
            }
            __syncthreads();
        }
    }

    // epilogue: bias + tanh + bf16 split -> g_H1h/g_H1l
    const float* bb = b0 + k * DFF + nb + wn * 32;
    #pragma unroll
    for (int nf = 0; nf < 4; nf++) {
        float2 bias = *reinterpret_cast<const float2*>(&bb[nf * 8 + 2 * (lane & 3)]);
        int n = nb + wn * 32 + nf * 8 + 2 * (lane & 3);
        #pragma unroll
        for (int mf = 0; mf < 4; mf++) {
            #pragma unroll
            for (int h = 0; h < 2; h++) {
                int m = mb + wm * 64 + mf * 16 + (lane >> 2) + h * 8;
                float v0 = tanhf(acc[mf][nf][h * 2 + 0] + bias.x);
                float v1 = tanhf(acc[mf][nf][h * 2 + 1] + bias.y);
                uint32_t H, L;
                split2(v0, v1, H, L);
                size_t off = ((size_t)k * MM + m) * DFF + n;
                *reinterpret_cast<uint32_t*>(g_H1h + off) = H;
                *reinterpret_cast<uint32_t*>(g_H1l + off) = L;
            }
        }
    }
}

// ---------------------------------------------------------------------------
// GEMM2 (mma.sync bf16, 3-term): C = H1[k] @ W1T[k]^T + b1; GLU; scatter-add.
//   Block 128x96 (full N), K-step 32 (48 iters). 8 warps as 4(M)x2(N).
// ---------------------------------------------------------------------------
#define G2_STAGE 28672
#define G2_SMEM  (2*G2_STAGE)

__global__ __launch_bounds__(256, 2) void gemm2_mma(
    const float* __restrict__ b1, float* __restrict__ out)
{
    extern __shared__ char smem[];
    const uint32_t sb = smem_u32(smem);
    const int t = threadIdx.x, wid = t >> 5, lane = t & 31;
    const int k = blockIdx.y, mb = blockIdx.x * 128;
    const int wm = wid & 3, wn = wid >> 2;

    const __nv_bfloat16* gA0 = g_H1h + ((size_t)k * MM + mb) * DFF;
    const __nv_bfloat16* gA1 = g_H1l + ((size_t)k * MM + mb) * DFF;
    const __nv_bfloat16* gB0 = g_W1T_hi + (size_t)k * NOUT * DFF;
    const __nv_bfloat16* gB1 = g_W1T_lo + (size_t)k * NOUT * DFF;

    const __nv_bfloat16* gbase[7];
    uint32_t sdst[7];
    #pragma unroll
    for (int j = 0; j < 7; j++) {
        int id = t + j * 256;
        if (id < 1024) {
            int mat = id >> 9, r = (id >> 2) & 127, c = id & 3;
            gbase[j] = ((mat == 0) ? gA0 : gA1) + (size_t)r * DFF + c * 8;
            sdst[j]  = (uint32_t)(mat * 8192) + tswz(r, c);
        } else {
            int id2 = id - 1024;
            int mat = (id2 >= 384);
            int rr = id2 - mat * 384;
            int r = rr >> 2, c = rr & 3;
            gbase[j] = ((mat == 0) ? gB0 : gB1) + (size_t)r * DFF + c * 8;
            sdst[j]  = 16384u + (uint32_t)(mat * 6144) + tswz(r, c);
        }
    }

    const uint32_t laneXor = (uint32_t)((lane >> 4) << 4);
    uint32_t aHiO[2], aLoO[2], bHiO[3], bLoO[3];
    #pragma unroll
    for (int mf = 0; mf < 2; mf++) {
        uint32_t o = tswz(wm * 32 + mf * 16 + (lane & 15), 0) ^ laneXor;
        aHiO[mf] = o; aLoO[mf] = o + 8192;
    }
    #pragma unroll
    for (int g = 0; g < 3; g++) {
        uint32_t o = tswz(wn * 48 + g * 16 + (lane & 15), 0) ^ laneXor;
        bHiO[g] = o + 16384; bLoO[g] = o + 22528;
    }

    float acc[2][6][4];
    #pragma unroll
    for (int a = 0; a < 2; a++)
        #pragma unroll
        for (int b = 0; b < 6; b++)
            #pragma unroll
            for (int c = 0; c < 4; c++) acc[a][b][c] = 0.f;

    #pragma unroll
    for (int j = 0; j < 7; j++) CP16(sb + sdst[j], gbase[j]);
    CP_COMMIT();

    #pragma unroll 1
    for (int it2 = 0; it2 < 24; ++it2) {
        #pragma unroll
        for (int half = 0; half < 2; half++) {
            const int it = it2 * 2 + half;
            const uint32_t stb = sb + (uint32_t)(half * G2_STAGE);
            if (it + 1 < 48) {
                const uint32_t stn = sb + (uint32_t)((half ^ 1) * G2_STAGE);
                const int k0 = (it + 1) * 32;
                #pragma unroll
                for (int j = 0; j < 7; j++) CP16(stn + sdst[j], gbase[j] + k0);
                CP_COMMIT();
                CP_WAIT1();
            } else {
                CP_WAIT0();
            }
            __syncthreads();

            #pragma unroll
            for (int kc = 0; kc < 2; kc++) {
                const uint32_t kx = (uint32_t)(kc << 5);
                uint32_t ah[2][4], al[2][4], bh[3][4], bl[3][4];
                #pragma unroll
                for (int mf = 0; mf < 2; mf++) {
                    ldsm4(ah[mf], stb + (aHiO[mf] ^ kx));
                    ldsm4(al[mf], stb + (aLoO[mf] ^ kx));
                }
                #pragma unroll
                for (int g = 0; g < 3; g++) {
                    ldsm4(bh[g], stb + (bHiO[g] ^ kx));
                    ldsm4(bl[g], stb + (bLoO[g] ^ kx));
                }
                #pragma unroll
                for (int mf = 0; mf < 2; mf++)
                    #pragma unroll
                    for (int nf = 0; nf < 6; nf++) {
                        int g = nf >> 1, s = nf & 1;
                        mma_bf16(acc[mf][nf], ah[mf], bh[g][s], bh[g][s + 2]);
                        mma_bf16(acc[mf][nf], ah[mf], bl[g][s], bl[g][s + 2]);
                        mma_bf16(acc[mf][nf], al[mf], bh[g][s], bh[g][s + 2]);
                    }
            }
            __syncthreads();
        }
    }

    // epilogue: stage C in smem, then GLU + scatter-add
    float* Cs = reinterpret_cast<float*>(smem);   // 128 x 100 floats
    #pragma unroll
    for (int nf = 0; nf < 6; nf++) {
        int n = wn * 48 + nf * 8 + 2 * (lane & 3);
        #pragma unroll
        for (int mf = 0; mf < 2; mf++) {
            #pragma unroll
            for (int h = 0; h < 2; h++) {
                int m = wm * 32 + mf * 16 + (lane >> 2) + h * 8;
                float2 v;
                v.x = acc[mf][nf][h * 2 + 0];
                v.y = acc[mf][nf][h * 2 + 1];
                *reinterpret_cast<float2*>(&Cs[m * 100 + n]) = v;
            }
        }
    }
    __syncthreads();

    {
        int m = t >> 1;
        int j0 = (t & 1) * 24;
        int gm = mb + m, bidx = gm >> 9, tidx = gm & 511;
        const float* bA = b1 + k * NOUT;
        #pragma unroll
        for (int jj = 0; jj < 24; jj++) {
            int j = j0 + jj;
            float a = Cs[m * 100 + j]      + bA[j];
            float g = Cs[m * 100 + j + 48] + bA[j + 48];
            float ch = a * (1.0f / (1.0f + __expf(-g)));
            int p = k * 32 + j;
            int oi = ((bidx * 2 + (p & 1)) * TT + tidx) * FREQ + (p >> 1);
            atomicAdd(&out[oi], ch);
        }
    }
}

// ---------------------------------------------------------------------------
extern "C" void kernel_launch(void* const* d_in, const int* in_sizes, int n_in,
                              void* d_out, int out_size)
{
    (void)in_sizes; (void)n_in;
    const float* x     = (const float*)d_in[0];
    const float* gamma = (const float*)d_in[1];
    const float* W0    = (const float*)d_in[2];
    const float* b0    = (const float*)d_in[3];
    const float* W1    = (const float*)d_in[4];
    const float* b1    = (const float*)d_in[5];
    float*       out   = (float*)d_out;

    cudaFuncSetAttribute(gemm1_mma, cudaFuncAttributeMaxDynamicSharedMemorySize, G1_SMEM);
    cudaFuncSetAttribute(gemm2_mma, cudaFuncAttributeMaxDynamicSharedMemorySize, G2_SMEM);

    cudaMemsetAsync(out, 0, (size_t)out_size * sizeof(float));

    {
        dim3 b(32, 8);
        dim3 g0(DFF / 32, DD / 32, KK);
        transpose_split_kernel<0><<<g0, b>>>(W0, DD, DFF);
        dim3 g1(NOUT / 32, DFF / 32, KK);
        transpose_split_kernel<1><<<g1, b>>>(W1, DFF, NOUT);
    }

    rms_split_kernel<<<(MM * KK * 32 + 255) / 256, 256>>>(x, gamma);

    dim3 g1(DFF / 128, MM / 128, KK);      // (12, 16, 63)
    gemm1_mma<<<g1, 256, G1_SMEM>>>(b0);

    dim3 g2(MM / 128, KK);                 // (16, 63)
    gemm2_mma<<<g2, 256, G2_SMEM>>>(b1, out);
}

// round 6
// speedup vs baseline: 1.1264x; 1.1264x over previous
#include <cuda_runtime.h>
#include <cuda_fp16.h>
#include <cstdint>

// Problem constants
#define BB   4
#define TT   512
#define KK   63
#define DD   384
#define DFF  1536
#define MM   (BB*TT)          // 2048
#define NOUT 96
#define FREQ 1016

// ---------------------------------------------------------------------------
// Scratch (device globals; ONLY referenced from device code — see R3 bug).
// A-side (activations) split hi/lo fp16; weights single fp16.
// ---------------------------------------------------------------------------
__device__ __align__(16) __half g_An_hi[(size_t)KK * MM * DD];
__device__ __align__(16) __half g_An_lo[(size_t)KK * MM * DD];
__device__ __align__(16) __half g_W0T [(size_t)KK * DFF * DD];
__device__ __align__(16) __half g_W1T [(size_t)KK * NOUT * DFF];
__device__ __align__(16) __half g_H1h [(size_t)KK * MM * DFF];
__device__ __align__(16) __half g_H1l [(size_t)KK * MM * DFF];

// ---------------------------------------------------------------------------
// Portable PTX helpers (plain sm_103)
// ---------------------------------------------------------------------------
__device__ __forceinline__ uint32_t smem_u32(const void* p) {
    uint32_t a;
    asm("{ .reg .u64 t; cvta.to.shared.u64 t, %1; cvt.u32.u64 %0, t; }"
        : "=r"(a) : "l"(p));
    return a;
}
#define CP16(dst, src) \
    asm volatile("cp.async.cg.shared.global [%0], [%1], 16;" \
                 :: "r"(dst), "l"(src) : "memory")
#define CP_COMMIT() asm volatile("cp.async.commit_group;" ::: "memory")
#define CP_WAIT1()  asm volatile("cp.async.wait_group 1;"  ::: "memory")
#define CP_WAIT0()  asm volatile("cp.async.wait_group 0;"  ::: "memory")

__device__ __forceinline__ void ldsm4(uint32_t r[4], uint32_t addr) {
    asm volatile("ldmatrix.sync.aligned.m8n8.x4.shared.b16 {%0,%1,%2,%3}, [%4];"
        : "=r"(r[0]), "=r"(r[1]), "=r"(r[2]), "=r"(r[3]) : "r"(addr));
}
__device__ __forceinline__ void mma_f16(float c[4], const uint32_t a[4],
                                        uint32_t b0, uint32_t b1) {
    asm volatile(
        "mma.sync.aligned.m16n8k16.row.col.f32.f16.f16.f32 "
        "{%0,%1,%2,%3}, {%4,%5,%6,%7}, {%8,%9}, {%0,%1,%2,%3};"
        : "+f"(c[0]), "+f"(c[1]), "+f"(c[2]), "+f"(c[3])
        : "r"(a[0]), "r"(a[1]), "r"(a[2]), "r"(a[3]), "r"(b0), "r"(b1));
}

// Swizzled byte offset inside a [rows x 32 halves] tile packed as 128B lines
// (2 rows/line). Property: tswz(r,c) == tswz(r,0) ^ (c<<4).
__device__ __forceinline__ uint32_t tswz(int r, int c) {
    uint32_t line = (uint32_t)r >> 1;
    uint32_t pos  = ((((uint32_t)r & 1u) << 2) | (uint32_t)c) ^ (line & 7u);
    return line * 128u + pos * 16u;
}

__device__ __forceinline__ void split2h(float a, float b, uint32_t& hi, uint32_t& lo) {
    __half ha = __float2half_rn(a), hb = __float2half_rn(b);
    float ra = a - __half2float(ha);
    float rb = b - __half2float(hb);
    __half2 H; H.x = ha; H.y = hb;
    __half2 L = __floats2half2_rn(ra, rb);
    hi = *reinterpret_cast<uint32_t*>(&H);
    lo = *reinterpret_cast<uint32_t*>(&L);
}

// ---------------------------------------------------------------------------
// RMSNorm + gamma + fp16 hi/lo split.  x[m][k][d] -> An[k][m][d]
// ---------------------------------------------------------------------------
__global__ __launch_bounds__(256) void rms_split_kernel(
    const float* __restrict__ x, const float* __restrict__ gamma)
{
    int gt = blockIdx.x * blockDim.x + threadIdx.x;
    int row = gt >> 5, lane = gt & 31;
    if (row >= MM * KK) return;
    int m = row / KK, k = row - m * KK;

    const float* xr = x + (size_t)row * DD;
    float4 v[3];
    float s = 0.f;
    #pragma unroll
    for (int i = 0; i < 3; i++) {
        v[i] = *reinterpret_cast<const float4*>(&xr[(lane + i * 32) * 4]);
        s += v[i].x*v[i].x + v[i].y*v[i].y + v[i].z*v[i].z + v[i].w*v[i].w;
    }
    #pragma unroll
    for (int o = 16; o > 0; o >>= 1) s += __shfl_xor_sync(0xffffffffu, s, o);
    s = rsqrtf(s * (1.0f / DD) + 1e-8f);

    const float* gk = gamma + k * DD;
    __half* oh = g_An_hi + ((size_t)k * MM + m) * DD;
    __half* ol = g_An_lo + ((size_t)k * MM + m) * DD;
    #pragma unroll
    for (int i = 0; i < 3; i++) {
        int d = (lane + i * 32) * 4;
        float4 g = *reinterpret_cast<const float4*>(&gk[d]);
        float a0 = v[i].x*s*g.x, a1 = v[i].y*s*g.y, a2 = v[i].z*s*g.z, a3 = v[i].w*s*g.w;
        uint2 H, L;
        split2h(a0, a1, H.x, L.x);
        split2h(a2, a3, H.y, L.y);
        *reinterpret_cast<uint2*>(oh + d) = H;
        *reinterpret_cast<uint2*>(ol + d) = L;
    }
}

// ---------------------------------------------------------------------------
// Per-band transpose + single fp16 round. in[k][R][C] -> dst[k][C][R]
// ---------------------------------------------------------------------------
template <int SEL>
__global__ __launch_bounds__(256) void transpose_h_kernel(
    const float* __restrict__ in, int R, int C)
{
    __half* __restrict__ oh = (SEL == 0) ? g_W0T : g_W1T;

    __shared__ float tile[32][33];
    const float* inp = in + (size_t)blockIdx.z * R * C;
    size_t obase = (size_t)blockIdx.z * C * R;
    int r0 = blockIdx.y * 32, c0 = blockIdx.x * 32;
    int tx = threadIdx.x, ty = threadIdx.y;

    #pragma unroll
    for (int j = 0; j < 4; j++)
        tile[ty + 8*j][tx] = inp[(size_t)(r0 + ty + 8*j) * C + c0 + tx];
    __syncthreads();
    #pragma unroll
    for (int j = 0; j < 4; j++) {
        int oc = c0 + ty + 8*j;
        oh[obase + (size_t)oc * R + r0 + tx] = __float2half_rn(tile[tx][ty + 8*j]);
    }
}

// ---------------------------------------------------------------------------
// GEMM1 (mma.sync f16, 2-term): H1[k] = tanh(An[k] @ W0T[k]^T + b0[k])
//   Block 128(M) x 256(N), K-step 32 (12 iters), cp.async double buffer.
//   8 warps as 2(M) x 4(N): warp tile 64x64.
//   Stage: Ahi 8K | Alo 8K | B 16K = 32KB; 2 stages = 64KB.
// ---------------------------------------------------------------------------
#define G1_STAGE 32768
#define G1_SMEM  (2*G1_STAGE)

__global__ __launch_bounds__(256, 1) void gemm1_mma(const float* __restrict__ b0)
{
    extern __shared__ char smem[];
    const uint32_t sb = smem_u32(smem);
    const int t = threadIdx.x, wid = t >> 5, lane = t & 31;
    const int k = blockIdx.z, mb = blockIdx.y * 128, nb = blockIdx.x * 256;
    const int wm = wid & 1, wn = wid >> 1;

    const __half* gA0 = g_An_hi + ((size_t)k * MM  + mb) * DD;
    const __half* gA1 = g_An_lo + ((size_t)k * MM  + mb) * DD;
    const __half* gB  = g_W0T   + ((size_t)k * DFF + nb) * DD;

    // 8 cp.async chunks/thread: ids 0..511 Ahi, 512..1023 Alo, 1024..2047 B
    const __half* gbase[8];
    uint32_t sdst[8];
    #pragma unroll
    for (int j = 0; j < 8; j++) {
        int id = t + j * 256;
        int c = id & 3;
        if (id < 1024) {
            int mat = id >> 9, r = (id >> 2) & 127;
            gbase[j] = ((mat == 0) ? gA0 : gA1) + (size_t)r * DD + c * 8;
            sdst[j]  = (uint32_t)(mat * 8192) + tswz(r, c);
        } else {
            int r = (id - 1024) >> 2;            // 0..255
            gbase[j] = gB + (size_t)r * DD + c * 8;
            sdst[j]  = 16384u + tswz(r, c);
        }
    }

    // ldmatrix base offsets (k-chunk folded in-loop via XOR)
    const uint32_t laneXor = (uint32_t)((lane >> 4) << 4);
    uint32_t aHiO[4], aLoO[4], bO[4];
    #pragma unroll
    for (int mf = 0; mf < 4; mf++) {
        uint32_t o = tswz(wm * 64 + mf * 16 + (lane & 15), 0) ^ laneXor;
        aHiO[mf] = o; aLoO[mf] = o + 8192;
    }
    #pragma unroll
    for (int g = 0; g < 4; g++)
        bO[g] = (tswz(wn * 64 + g * 16 + (lane & 15), 0) ^ laneXor) + 16384;

    float acc[4][8][4];
    #pragma unroll
    for (int a = 0; a < 4; a++)
        #pragma unroll
        for (int b = 0; b < 8; b++)
            #pragma unroll
            for (int c = 0; c < 4; c++) acc[a][b][c] = 0.f;

    #pragma unroll
    for (int j = 0; j < 8; j++) CP16(sb + sdst[j], gbase[j]);
    CP_COMMIT();

    #pragma unroll 1
    for (int it2 = 0; it2 < 6; ++it2) {
        #pragma unroll
        for (int half = 0; half < 2; half++) {
            const int it = it2 * 2 + half;
            const uint32_t stb = sb + (uint32_t)(half * G1_STAGE);
            if (it + 1 < 12) {
                const uint32_t stn = sb + (uint32_t)((half ^ 1) * G1_STAGE);
                const int k0 = (it + 1) * 32;
                #pragma unroll
                for (int j = 0; j < 8; j++) CP16(stn + sdst[j], gbase[j] + k0);
                CP_COMMIT();
                CP_WAIT1();
            } else {
                CP_WAIT0();
            }
            __syncthreads();

            #pragma unroll
            for (int kc = 0; kc < 2; kc++) {
                const uint32_t kx = (uint32_t)(kc << 5);
                uint32_t b[4][4], ah[4][4], al[4][4];
                #pragma unroll
                for (int g = 0; g < 4; g++) ldsm4(b[g], stb + (bO[g] ^ kx));
                #pragma unroll
                for (int mf = 0; mf < 4; mf++) ldsm4(ah[mf], stb + (aHiO[mf] ^ kx));
                #pragma unroll
                for (int mf = 0; mf < 4; mf++)
                    #pragma unroll
                    for (int nf = 0; nf < 8; nf++) {
                        int g = nf >> 1, s = nf & 1;
                        mma_f16(acc[mf][nf], ah[mf], b[g][s], b[g][s + 2]);
                    }
                #pragma unroll
                for (int mf = 0; mf < 4; mf++) ldsm4(al[mf], stb + (aLoO[mf] ^ kx));
                #pragma unroll
                for (int mf = 0; mf < 4; mf++)
                    #pragma unroll
                    for (int nf = 0; nf < 8; nf++) {
                        int g = nf >> 1, s = nf & 1;
                        mma_f16(acc[mf][nf], al[mf], b[g][s], b[g][s + 2]);
                    }
            }
            __syncthreads();
        }
    }

    // epilogue: bias + tanh + fp16 split -> g_H1h/g_H1l
    #pragma unroll
    for (int nf = 0; nf < 8; nf++) {
        int n = nb + wn * 64 + nf * 8 + 2 * (lane & 3);
        float2 bias = *reinterpret_cast<const float2*>(&b0[k * DFF + n]);
        #pragma unroll
        for (int mf = 0; mf < 4; mf++) {
            #pragma unroll
            for (int h = 0; h < 2; h++) {
                int m = mb + wm * 64 + mf * 16 + (lane >> 2) + h * 8;
                float v0 = tanhf(acc[mf][nf][h * 2 + 0] + bias.x);
                float v1 = tanhf(acc[mf][nf][h * 2 + 1] + bias.y);
                uint32_t H, L;
                split2h(v0, v1, H, L);
                size_t off = ((size_t)k * MM + m) * DFF + n;
                *reinterpret_cast<uint32_t*>(g_H1h + off) = H;
                *reinterpret_cast<uint32_t*>(g_H1l + off) = L;
            }
        }
    }
}

// ---------------------------------------------------------------------------
// GEMM2 (mma.sync f16, 2-term): C = H1[k] @ W1T[k]^T + b1; GLU; scatter-add.
//   Block 256(M) x 96(N), K-step 32 (48 iters). 8 warps as 4(M) x 2(N): 64x48.
//   Stage: Ahi 16K | Alo 16K | B 6K = 38KB; 2 stages = 76KB.
//   Epilogue Cs = 256x100 f32 = 100KB (reuses smem).
// ---------------------------------------------------------------------------
#define G2_STAGE 38912
#define G2_SMEM  102400

__global__ __launch_bounds__(256, 1) void gemm2_mma(
    const float* __restrict__ b1, float* __restrict__ out)
{
    extern __shared__ char smem[];
    const uint32_t sb = smem_u32(smem);
    const int t = threadIdx.x, wid = t >> 5, lane = t & 31;
    const int k = blockIdx.y, mb = blockIdx.x * 256;
    const int wm = wid & 3, wn = wid >> 2;

    const __half* gA0 = g_H1h + ((size_t)k * MM + mb) * DFF;
    const __half* gA1 = g_H1l + ((size_t)k * MM + mb) * DFF;
    const __half* gB  = g_W1T + (size_t)k * NOUT * DFF;

    // cp ids: 0..1023 Ahi, 1024..2047 Alo, 2048..2431 B  (10/thread, guarded)
    const __half* gbase[10];
    uint32_t sdst[10];
    #pragma unroll
    for (int j = 0; j < 10; j++) {
        int id = t + j * 256;
        if (id >= 2432) { gbase[j] = nullptr; sdst[j] = 0; continue; }
        int c = id & 3;
        if (id < 2048) {
            int mat = id >> 10, r = (id >> 2) & 255;
            gbase[j] = ((mat == 0) ? gA0 : gA1) + (size_t)r * DFF + c * 8;
            sdst[j]  = (uint32_t)(mat * 16384) + tswz(r, c);
        } else {
            int r = (id - 2048) >> 2;            // 0..95
            gbase[j] = gB + (size_t)r * DFF + c * 8;
            sdst[j]  = 32768u + tswz(r, c);
        }
    }

    const uint32_t laneXor = (uint32_t)((lane >> 4) << 4);
    uint32_t aHiO[4], aLoO[4], bO[3];
    #pragma unroll
    for (int mf = 0; mf < 4; mf++) {
        uint32_t o = tswz(wm * 64 + mf * 16 + (lane & 15), 0) ^ laneXor;
        aHiO[mf] = o; aLoO[mf] = o + 16384;
    }
    #pragma unroll
    for (int g = 0; g < 3; g++)
        bO[g] = (tswz(wn * 48 + g * 16 + (lane & 15), 0) ^ laneXor) + 32768;

    float acc[4][6][4];
    #pragma unroll
    for (int a = 0; a < 4; a++)
        #pragma unroll
        for (int b = 0; b < 6; b++)
            #pragma unroll
            for (int c = 0; c < 4; c++) acc[a][b][c] = 0.f;

    #pragma unroll
    for (int j = 0; j < 10; j++) if (gbase[j]) CP16(sb + sdst[j], gbase[j]);
    CP_COMMIT();

    #pragma unroll 1
    for (int it2 = 0; it2 < 24; ++it2) {
        #pragma unroll
        for (int half = 0; half < 2; half++) {
            const int it = it2 * 2 + half;
            const uint32_t stb = sb + (uint32_t)(half * G2_STAGE);
            if (it + 1 < 48) {
                const uint32_t stn = sb + (uint32_t)((half ^ 1) * G2_STAGE);
                const int k0 = (it + 1) * 32;
                #pragma unroll
                for (int j = 0; j < 10; j++)
                    if (gbase[j]) CP16(stn + sdst[j], gbase[j] + k0);
                CP_COMMIT();
                CP_WAIT1();
            } else {
                CP_WAIT0();
            }
            __syncthreads();

            #pragma unroll
            for (int kc = 0; kc < 2; kc++) {
                const uint32_t kx = (uint32_t)(kc << 5);
                uint32_t b[3][4], ah[4][4], al[4][4];
                #pragma unroll
                for (int g = 0; g < 3; g++) ldsm4(b[g], stb + (bO[g] ^ kx));
                #pragma unroll
                for (int mf = 0; mf < 4; mf++) ldsm4(ah[mf], stb + (aHiO[mf] ^ kx));
                #pragma unroll
                for (int mf = 0; mf < 4; mf++)
                    #pragma unroll
                    for (int nf = 0; nf < 6; nf++) {
                        int g = nf >> 1, s = nf & 1;
                        mma_f16(acc[mf][nf], ah[mf], b[g][s], b[g][s + 2]);
                    }
                #pragma unroll
                for (int mf = 0; mf < 4; mf++) ldsm4(al[mf], stb + (aLoO[mf] ^ kx));
                #pragma unroll
                for (int mf = 0; mf < 4; mf++)
                    #pragma unroll
                    for (int nf = 0; nf < 6; nf++) {
                        int g = nf >> 1, s = nf & 1;
                        mma_f16(acc[mf][nf], al[mf], b[g][s], b[g][s + 2]);
                    }
            }
            __syncthreads();
        }
    }

    // epilogue: stage C (256x100) in smem, then GLU + scatter-add
    float* Cs = reinterpret_cast<float*>(smem);
    #pragma unroll
    for (int nf = 0; nf < 6; nf++) {
        int n = wn * 48 + nf * 8 + 2 * (lane & 3);
        #pragma unroll
        for (int mf = 0; mf < 4; mf++) {
            #pragma unroll
            for (int h = 0; h < 2; h++) {
                int m = wm * 64 + mf * 16 + (lane >> 2) + h * 8;
                float2 v;
                v.x = acc[mf][nf][h * 2 + 0];
                v.y = acc[mf][nf][h * 2 + 1];
                *reinterpret_cast<float2*>(&Cs[m * 100 + n]) = v;
            }
        }
    }
    __syncthreads();

    {
        int m = t;
        int gm = mb + m, bidx = gm >> 9, tidx = gm & 511;
        const float* bA = b1 + k * NOUT;
        #pragma unroll 4
        for (int j = 0; j < 48; j++) {
            float a = Cs[m * 100 + j]      + bA[j];
            float g = Cs[m * 100 + j + 48] + bA[j + 48];
            float ch = a * (1.0f / (1.0f + __expf(-g)));
            int p = k * 32 + j;
            int oi = ((bidx * 2 + (p & 1)) * TT + tidx) * FREQ + (p >> 1);
            atomicAdd(&out[oi], ch);
        }
    }
}

// ---------------------------------------------------------------------------
extern "C" void kernel_launch(void* const* d_in, const int* in_sizes, int n_in,
                              void* d_out, int out_size)
{
    (void)in_sizes; (void)n_in;
    const float* x     = (const float*)d_in[0];
    const float* gamma = (const float*)d_in[1];
    const float* W0    = (const float*)d_in[2];
    const float* b0    = (const float*)d_in[3];
    const float* W1    = (const float*)d_in[4];
    const float* b1    = (const float*)d_in[5];
    float*       out   = (float*)d_out;

    cudaFuncSetAttribute(gemm1_mma, cudaFuncAttributeMaxDynamicSharedMemorySize, G1_SMEM);
    cudaFuncSetAttribute(gemm2_mma, cudaFuncAttributeMaxDynamicSharedMemorySize, G2_SMEM);

    cudaMemsetAsync(out, 0, (size_t)out_size * sizeof(float));

    {
        dim3 b(32, 8);
        dim3 g0(DFF / 32, DD / 32, KK);    // W0 [k][384][1536] -> [k][1536][384]
        transpose_h_kernel<0><<<g0, b>>>(W0, DD, DFF);
        dim3 g1(NOUT / 32, DFF / 32, KK);  // W1 [k][1536][96] -> [k][96][1536]
        transpose_h_kernel<1><<<g1, b>>>(W1, DFF, NOUT);
    }

    rms_split_kernel<<<(MM * KK * 32 + 255) / 256, 256>>>(x, gamma);

    dim3 g1(DFF / 256, MM / 128, KK);      // (6, 16, 63)
    gemm1_mma<<<g1, 256, G1_SMEM>>>(b0);

    dim3 g2(MM / 256, KK);                 // (8, 63)
    gemm2_mma<<<g2, 256, G2_SMEM>>>(b1, out);
}

// round 7
// speedup vs baseline: 1.3045x; 1.1581x over previous
#include <cuda_runtime.h>
#include <cuda_fp16.h>
#include <cstdint>

// Problem constants
#define BB   4
#define TT   512
#define KK   63
#define DD   384
#define DFF  1536
#define MM   (BB*TT)          // 2048
#define NOUT 96
#define FREQ 1016

// ---------------------------------------------------------------------------
// Scratch (device globals; ONLY referenced from device code — see R3 bug).
// ---------------------------------------------------------------------------
__device__ __align__(16) __half g_An_hi[(size_t)KK * MM * DD];
__device__ __align__(16) __half g_An_lo[(size_t)KK * MM * DD];
__device__ __align__(16) __half g_W0T [(size_t)KK * DFF * DD];
__device__ __align__(16) __half g_W1T [(size_t)KK * NOUT * DFF];
__device__ __align__(16) __half g_H1h [(size_t)KK * MM * DFF];
__device__ __align__(16) __half g_H1l [(size_t)KK * MM * DFF];

// ---------------------------------------------------------------------------
// Portable PTX helpers (plain sm_103)
// ---------------------------------------------------------------------------
__device__ __forceinline__ uint32_t smem_u32(const void* p) {
    uint32_t a;
    asm("{ .reg .u64 t; cvta.to.shared.u64 t, %1; cvt.u32.u64 %0, t; }"
        : "=r"(a) : "l"(p));
    return a;
}
#define CP16(dst, src) \
    asm volatile("cp.async.cg.shared.global [%0], [%1], 16;" \
                 :: "r"(dst), "l"(src) : "memory")
#define CP_COMMIT() asm volatile("cp.async.commit_group;" ::: "memory")
#define CP_WAITN(n) asm volatile("cp.async.wait_group %0;" :: "n"(n) : "memory")

__device__ __forceinline__ void ldsm4(uint32_t r[4], uint32_t addr) {
    asm volatile("ldmatrix.sync.aligned.m8n8.x4.shared.b16 {%0,%1,%2,%3}, [%4];"
        : "=r"(r[0]), "=r"(r[1]), "=r"(r[2]), "=r"(r[3]) : "r"(addr));
}
__device__ __forceinline__ void mma_f16(float c[4], const uint32_t a[4],
                                        uint32_t b0, uint32_t b1) {
    asm volatile(
        "mma.sync.aligned.m16n8k16.row.col.f32.f16.f16.f32 "
        "{%0,%1,%2,%3}, {%4,%5,%6,%7}, {%8,%9}, {%0,%1,%2,%3};"
        : "+f"(c[0]), "+f"(c[1]), "+f"(c[2]), "+f"(c[3])
        : "r"(a[0]), "r"(a[1]), "r"(a[2]), "r"(a[3]), "r"(b0), "r"(b1));
}

// Swizzled byte offset in a [rows x 32 halves] tile packed as 128B lines
// (2 rows/line). Property: tswz(r,c) == tswz(r,0) ^ (c<<4).
__device__ __forceinline__ uint32_t tswz(int r, int c) {
    uint32_t line = (uint32_t)r >> 1;
    uint32_t pos  = ((((uint32_t)r & 1u) << 2) | (uint32_t)c) ^ (line & 7u);
    return line * 128u + pos * 16u;
}

__device__ __forceinline__ void split2h(float a, float b, uint32_t& hi, uint32_t& lo) {
    __half ha = __float2half_rn(a), hb = __float2half_rn(b);
    float ra = a - __half2float(ha);
    float rb = b - __half2float(hb);
    __half2 H; H.x = ha; H.y = hb;
    __half2 L = __floats2half2_rn(ra, rb);
    hi = *reinterpret_cast<uint32_t*>(&H);
    lo = *reinterpret_cast<uint32_t*>(&L);
}

// ---------------------------------------------------------------------------
// RMSNorm + gamma + fp16 hi/lo split.  x[m][k][d] -> An[k][m][d]
// ---------------------------------------------------------------------------
__global__ __launch_bounds__(256) void rms_split_kernel(
    const float* __restrict__ x, const float* __restrict__ gamma)
{
    int gt = blockIdx.x * blockDim.x + threadIdx.x;
    int row = gt >> 5, lane = gt & 31;
    if (row >= MM * KK) return;
    int m = row / KK, k = row - m * KK;

    const float* xr = x + (size_t)row * DD;
    float4 v[3];
    float s = 0.f;
    #pragma unroll
    for (int i = 0; i < 3; i++) {
        v[i] = *reinterpret_cast<const float4*>(&xr[(lane + i * 32) * 4]);
        s += v[i].x*v[i].x + v[i].y*v[i].y + v[i].z*v[i].z + v[i].w*v[i].w;
    }
    #pragma unroll
    for (int o = 16; o > 0; o >>= 1) s += __shfl_xor_sync(0xffffffffu, s, o);
    s = rsqrtf(s * (1.0f / DD) + 1e-8f);

    const float* gk = gamma + k * DD;
    __half* oh = g_An_hi + ((size_t)k * MM + m) * DD;
    __half* ol = g_An_lo + ((size_t)k * MM + m) * DD;
    #pragma unroll
    for (int i = 0; i < 3; i++) {
        int d = (lane + i * 32) * 4;
        float4 g = *reinterpret_cast<const float4*>(&gk[d]);
        float a0 = v[i].x*s*g.x, a1 = v[i].y*s*g.y, a2 = v[i].z*s*g.z, a3 = v[i].w*s*g.w;
        uint2 H, L;
        split2h(a0, a1, H.x, L.x);
        split2h(a2, a3, H.y, L.y);
        *reinterpret_cast<uint2*>(oh + d) = H;
        *reinterpret_cast<uint2*>(ol + d) = L;
    }
}

// ---------------------------------------------------------------------------
// Per-band transpose + fp16 round. in[k][R][C] -> dst[k][C][R]
// ---------------------------------------------------------------------------
template <int SEL>
__global__ __launch_bounds__(256) void transpose_h_kernel(
    const float* __restrict__ in, int R, int C)
{
    __half* __restrict__ oh = (SEL == 0) ? g_W0T : g_W1T;

    __shared__ float tile[32][33];
    const float* inp = in + (size_t)blockIdx.z * R * C;
    size_t obase = (size_t)blockIdx.z * C * R;
    int r0 = blockIdx.y * 32, c0 = blockIdx.x * 32;
    int tx = threadIdx.x, ty = threadIdx.y;

    #pragma unroll
    for (int j = 0; j < 4; j++)
        tile[ty + 8*j][tx] = inp[(size_t)(r0 + ty + 8*j) * C + c0 + tx];
    __syncthreads();
    #pragma unroll
    for (int j = 0; j < 4; j++) {
        int oc = c0 + ty + 8*j;
        oh[obase + (size_t)oc * R + r0 + tx] = __float2half_rn(tile[tx][ty + 8*j]);
    }
}

// ---------------------------------------------------------------------------
// GEMM1 (mma.sync f16, 2-term): H1[k] = tanh(An[k] @ W0T[k]^T + b0[k])
//   Block 128x128, K-step 32 (12 iters), 3-stage cp.async.
//   8 warps as 2(M)x4(N): warp tile 64x32. 2 CTAs/SM.
//   Stage: Ahi 8K | Alo 8K | B 8K = 24KB; 3 stages = 72KB.
// ---------------------------------------------------------------------------
#define G1_STAGE 24576
#define G1_SMEM  (3*G1_STAGE)

__global__ __launch_bounds__(256, 2) void gemm1_mma(const float* __restrict__ b0)
{
    extern __shared__ char smem[];
    const uint32_t sb = smem_u32(smem);
    const int t = threadIdx.x, wid = t >> 5, lane = t & 31;
    const int k = blockIdx.z, mb = blockIdx.y * 128, nb = blockIdx.x * 128;
    const int wm = wid & 1, wn = wid >> 1;

    const __half* gA0 = g_An_hi + ((size_t)k * MM  + mb) * DD;
    const __half* gA1 = g_An_lo + ((size_t)k * MM  + mb) * DD;
    const __half* gB  = g_W0T   + ((size_t)k * DFF + nb) * DD;

    // 6 cp chunks/thread: 0..511 Ahi, 512..1023 Alo, 1024..1535 B
    const __half* gbase[6];
    uint32_t sdst[6];
    #pragma unroll
    for (int j = 0; j < 6; j++) {
        int id = t + j * 256;
        int c = id & 3, r = (id >> 2) & 127;
        if (id < 512)        { gbase[j] = gA0 + (size_t)r * DD + c * 8; sdst[j] = tswz(r, c); }
        else if (id < 1024)  { gbase[j] = gA1 + (size_t)r * DD + c * 8; sdst[j] = 8192u  + tswz(r, c); }
        else                 { gbase[j] = gB  + (size_t)r * DD + c * 8; sdst[j] = 16384u + tswz(r, c); }
    }

    const uint32_t laneXor = (uint32_t)((lane >> 4) << 4);
    uint32_t aHiO[4], aLoO[4], bO[2];
    #pragma unroll
    for (int mf = 0; mf < 4; mf++) {
        uint32_t o = tswz(wm * 64 + mf * 16 + (lane & 15), 0) ^ laneXor;
        aHiO[mf] = o; aLoO[mf] = o + 8192;
    }
    #pragma unroll
    for (int g = 0; g < 2; g++)
        bO[g] = (tswz(wn * 32 + g * 16 + (lane & 15), 0) ^ laneXor) + 16384;

    float acc[4][4][4];
    #pragma unroll
    for (int a = 0; a < 4; a++)
        #pragma unroll
        for (int b = 0; b < 4; b++)
            #pragma unroll
            for (int c = 0; c < 4; c++) acc[a][b][c] = 0.f;

    // prologue: stages 0 and 1
    #pragma unroll
    for (int j = 0; j < 6; j++) CP16(sb + sdst[j], gbase[j]);
    CP_COMMIT();
    #pragma unroll
    for (int j = 0; j < 6; j++) CP16(sb + G1_STAGE + sdst[j], gbase[j] + 32);
    CP_COMMIT();

    #pragma unroll 1
    for (int it3 = 0; it3 < 4; ++it3) {
        #pragma unroll
        for (int ph = 0; ph < 3; ph++) {
            const int it = it3 * 3 + ph;
            const uint32_t stb = sb + (uint32_t)(ph * G1_STAGE);
            if (it + 2 < 12) {
                const uint32_t stn = sb + (uint32_t)(((ph + 2) % 3) * G1_STAGE);
                const int k0 = (it + 2) * 32;
                #pragma unroll
                for (int j = 0; j < 6; j++) CP16(stn + sdst[j], gbase[j] + k0);
                CP_COMMIT();
                CP_WAITN(2);
            } else if (it + 1 < 12) {
                CP_WAITN(1);
            } else {
                CP_WAITN(0);
            }
            __syncthreads();

            #pragma unroll
            for (int kc = 0; kc < 2; kc++) {
                const uint32_t kx = (uint32_t)(kc << 5);
                uint32_t ah[4][4], al[4][4], b[2][4];
                #pragma unroll
                for (int g = 0; g < 2; g++) ldsm4(b[g], stb + (bO[g] ^ kx));
                #pragma unroll
                for (int mf = 0; mf < 4; mf++) ldsm4(ah[mf], stb + (aHiO[mf] ^ kx));
                #pragma unroll
                for (int mf = 0; mf < 4; mf++)
                    #pragma unroll
                    for (int nf = 0; nf < 4; nf++) {
                        int g = nf >> 1, s = nf & 1;
                        mma_f16(acc[mf][nf], ah[mf], b[g][s], b[g][s + 2]);
                    }
                #pragma unroll
                for (int mf = 0; mf < 4; mf++) ldsm4(al[mf], stb + (aLoO[mf] ^ kx));
                #pragma unroll
                for (int mf = 0; mf < 4; mf++)
                    #pragma unroll
                    for (int nf = 0; nf < 4; nf++) {
                        int g = nf >> 1, s = nf & 1;
                        mma_f16(acc[mf][nf], al[mf], b[g][s], b[g][s + 2]);
                    }
            }
            __syncthreads();
        }
    }

    // epilogue: bias + tanh + fp16 split -> g_H1h/g_H1l
    #pragma unroll
    for (int nf = 0; nf < 4; nf++) {
        int n = nb + wn * 32 + nf * 8 + 2 * (lane & 3);
        float2 bias = *reinterpret_cast<const float2*>(&b0[k * DFF + n]);
        #pragma unroll
        for (int mf = 0; mf < 4; mf++) {
            #pragma unroll
            for (int h = 0; h < 2; h++) {
                int m = mb + wm * 64 + mf * 16 + (lane >> 2) + h * 8;
                float v0 = tanhf(acc[mf][nf][h * 2 + 0] + bias.x);
                float v1 = tanhf(acc[mf][nf][h * 2 + 1] + bias.y);
                uint32_t H, L;
                split2h(v0, v1, H, L);
                size_t off = ((size_t)k * MM + m) * DFF + n;
                *reinterpret_cast<uint32_t*>(g_H1h + off) = H;
                *reinterpret_cast<uint32_t*>(g_H1l + off) = L;
            }
        }
    }
}

// ---------------------------------------------------------------------------
// GEMM2 (mma.sync f16, 2-term): C = H1[k] @ W1T[k]^T + b1; GLU; scatter-add.
//   Block 128x96, K-step 32 (48 iters), 3-stage cp.async.
//   8 warps as 4(M)x2(N): warp tile 32x48. 2 CTAs/SM.
//   Stage: Ahi 8K | Alo 8K | B 6K = 22528; 3 stages = 67584.
//   Epilogue Cs = 128x100 f32 = 51200 (fits in smem).
// ---------------------------------------------------------------------------
#define G2_STAGE 22528
#define G2_SMEM  (3*G2_STAGE)

__global__ __launch_bounds__(256, 2) void gemm2_mma(
    const float* __restrict__ b1, float* __restrict__ out)
{
    extern __shared__ char smem[];
    const uint32_t sb = smem_u32(smem);
    const int t = threadIdx.x, wid = t >> 5, lane = t & 31;
    const int k = blockIdx.y, mb = blockIdx.x * 128;
    const int wm = wid & 3, wn = wid >> 2;

    const __half* gA0 = g_H1h + ((size_t)k * MM + mb) * DFF;
    const __half* gA1 = g_H1l + ((size_t)k * MM + mb) * DFF;
    const __half* gB  = g_W1T + (size_t)k * NOUT * DFF;

    // 6 cp chunks/thread (guarded): 0..511 Ahi, 512..1023 Alo, 1024..1407 B
    const __half* gbase[6];
    uint32_t sdst[6];
    #pragma unroll
    for (int j = 0; j < 6; j++) {
        int id = t + j * 256;
        if (id >= 1408) { gbase[j] = nullptr; sdst[j] = 0; continue; }
        int c = id & 3, r = (id >> 2) & 127;
        if (id < 512)        { gbase[j] = gA0 + (size_t)r * DFF + c * 8; sdst[j] = tswz(r, c); }
        else if (id < 1024)  { gbase[j] = gA1 + (size_t)r * DFF + c * 8; sdst[j] = 8192u  + tswz(r, c); }
        else                 { int rb = (id - 1024) >> 2;
                               gbase[j] = gB + (size_t)rb * DFF + c * 8;
                               sdst[j]  = 16384u + tswz(rb, c); }
    }

    const uint32_t laneXor = (uint32_t)((lane >> 4) << 4);
    uint32_t aHiO[2], aLoO[2], bO[3];
    #pragma unroll
    for (int mf = 0; mf < 2; mf++) {
        uint32_t o = tswz(wm * 32 + mf * 16 + (lane & 15), 0) ^ laneXor;
        aHiO[mf] = o; aLoO[mf] = o + 8192;
    }
    #pragma unroll
    for (int g = 0; g < 3; g++)
        bO[g] = (tswz(wn * 48 + g * 16 + (lane & 15), 0) ^ laneXor) + 16384;

    float acc[2][6][4];
    #pragma unroll
    for (int a = 0; a < 2; a++)
        #pragma unroll
        for (int b = 0; b < 6; b++)
            #pragma unroll
            for (int c = 0; c < 4; c++) acc[a][b][c] = 0.f;

    #pragma unroll
    for (int j = 0; j < 6; j++) if (gbase[j]) CP16(sb + sdst[j], gbase[j]);
    CP_COMMIT();
    #pragma unroll
    for (int j = 0; j < 6; j++) if (gbase[j]) CP16(sb + G2_STAGE + sdst[j], gbase[j] + 32);
    CP_COMMIT();

    #pragma unroll 1
    for (int it3 = 0; it3 < 16; ++it3) {
        #pragma unroll
        for (int ph = 0; ph < 3; ph++) {
            const int it = it3 * 3 + ph;
            const uint32_t stb = sb + (uint32_t)(ph * G2_STAGE);
            if (it + 2 < 48) {
                const uint32_t stn = sb + (uint32_t)(((ph + 2) % 3) * G2_STAGE);
                const int k0 = (it + 2) * 32;
                #pragma unroll
                for (int j = 0; j < 6; j++)
                    if (gbase[j]) CP16(stn + sdst[j], gbase[j] + k0);
                CP_COMMIT();
                CP_WAITN(2);
            } else if (it + 1 < 48) {
                CP_WAITN(1);
            } else {
                CP_WAITN(0);
            }
            __syncthreads();

            #pragma unroll
            for (int kc = 0; kc < 2; kc++) {
                const uint32_t kx = (uint32_t)(kc << 5);
                uint32_t ah[2][4], al[2][4], b[3][4];
                #pragma unroll
                for (int g = 0; g < 3; g++) ldsm4(b[g], stb + (bO[g] ^ kx));
                #pragma unroll
                for (int mf = 0; mf < 2; mf++) ldsm4(ah[mf], stb + (aHiO[mf] ^ kx));
                #pragma unroll
                for (int mf = 0; mf < 2; mf++)
                    #pragma unroll
                    for (int nf = 0; nf < 6; nf++) {
                        int g = nf >> 1, s = nf & 1;
                        mma_f16(acc[mf][nf], ah[mf], b[g][s], b[g][s + 2]);
                    }
                #pragma unroll
                for (int mf = 0; mf < 2; mf++) ldsm4(al[mf], stb + (aLoO[mf] ^ kx));
                #pragma unroll
                for (int mf = 0; mf < 2; mf++)
                    #pragma unroll
                    for (int nf = 0; nf < 6; nf++) {
                        int g = nf >> 1, s = nf & 1;
                        mma_f16(acc[mf][nf], al[mf], b[g][s], b[g][s + 2]);
                    }
            }
            __syncthreads();
        }
    }

    // epilogue: stage C in smem, then GLU + scatter-add
    float* Cs = reinterpret_cast<float*>(smem);   // 128 x 100 floats
    #pragma unroll
    for (int nf = 0; nf < 6; nf++) {
        int n = wn * 48 + nf * 8 + 2 * (lane & 3);
        #pragma unroll
        for (int mf = 0; mf < 2; mf++) {
            #pragma unroll
            for (int h = 0; h < 2; h++) {
                int m = wm * 32 + mf * 16 + (lane >> 2) + h * 8;
                float2 v;
                v.x = acc[mf][nf][h * 2 + 0];
                v.y = acc[mf][nf][h * 2 + 1];
                *reinterpret_cast<float2*>(&Cs[m * 100 + n]) = v;
            }
        }
    }
    __syncthreads();

    {
        int m = t >> 1;
        int j0 = (t & 1) * 24;
        int gm = mb + m, bidx = gm >> 9, tidx = gm & 511;
        const float* bA = b1 + k * NOUT;
        #pragma unroll
        for (int jj = 0; jj < 24; jj++) {
            int j = j0 + jj;
            float a = Cs[m * 100 + j]      + bA[j];
            float g = Cs[m * 100 + j + 48] + bA[j + 48];
            float ch = a * (1.0f / (1.0f + __expf(-g)));
            int p = k * 32 + j;
            int oi = ((bidx * 2 + (p & 1)) * TT + tidx) * FREQ + (p >> 1);
            atomicAdd(&out[oi], ch);
        }
    }
}

// ---------------------------------------------------------------------------
extern "C" void kernel_launch(void* const* d_in, const int* in_sizes, int n_in,
                              void* d_out, int out_size)
{
    (void)in_sizes; (void)n_in;
    const float* x     = (const float*)d_in[0];
    const float* gamma = (const float*)d_in[1];
    const float* W0    = (const float*)d_in[2];
    const float* b0    = (const float*)d_in[3];
    const float* W1    = (const float*)d_in[4];
    const float* b1    = (const float*)d_in[5];
    float*       out   = (float*)d_out;

    cudaFuncSetAttribute(gemm1_mma, cudaFuncAttributeMaxDynamicSharedMemorySize, G1_SMEM);
    cudaFuncSetAttribute(gemm2_mma, cudaFuncAttributeMaxDynamicSharedMemorySize, G2_SMEM);

    cudaMemsetAsync(out, 0, (size_t)out_size * sizeof(float));

    {
        dim3 b(32, 8);
        dim3 g0(DFF / 32, DD / 32, KK);
        transpose_h_kernel<0><<<g0, b>>>(W0, DD, DFF);
        dim3 g1(NOUT / 32, DFF / 32, KK);
        transpose_h_kernel<1><<<g1, b>>>(W1, DFF, NOUT);
    }

    rms_split_kernel<<<(MM * KK * 32 + 255) / 256, 256>>>(x, gamma);

    dim3 g1(DFF / 128, MM / 128, KK);      // (12, 16, 63)
    gemm1_mma<<<g1, 256, G1_SMEM>>>(b0);

    dim3 g2(MM / 128, KK);                 // (16, 63)
    gemm2_mma<<<g2, 256, G2_SMEM>>>(b1, out);
}

// round 8
// speedup vs baseline: 1.3807x; 1.0585x over previous
#include <cuda_runtime.h>
#include <cuda_fp16.h>
#include <cstdint>

// Problem constants
#define BB   4
#define TT   512
#define KK   63
#define DD   384
#define DFF  1536
#define MM   (BB*TT)          // 2048
#define NOUT 96
#define FREQ 1016

// ---------------------------------------------------------------------------
// Scratch (device globals; ONLY referenced from device code — see R3 bug).
// ---------------------------------------------------------------------------
__device__ __align__(16) __half g_An_hi[(size_t)KK * MM * DD];
__device__ __align__(16) __half g_An_lo[(size_t)KK * MM * DD];
__device__ __align__(16) __half g_W0T [(size_t)KK * DFF * DD];
__device__ __align__(16) __half g_W1T [(size_t)KK * NOUT * DFF];
__device__ __align__(16) __half g_H1h [(size_t)KK * MM * DFF];
__device__ __align__(16) __half g_H1l [(size_t)KK * MM * DFF];

// ---------------------------------------------------------------------------
// Portable PTX helpers (plain sm_103)
// ---------------------------------------------------------------------------
__device__ __forceinline__ uint32_t smem_u32(const void* p) {
    uint32_t a;
    asm("{ .reg .u64 t; cvta.to.shared.u64 t, %1; cvt.u32.u64 %0, t; }"
        : "=r"(a) : "l"(p));
    return a;
}
#define CP16(dst, src) \
    asm volatile("cp.async.cg.shared.global [%0], [%1], 16;" \
                 :: "r"(dst), "l"(src) : "memory")
#define CP_COMMIT() asm volatile("cp.async.commit_group;" ::: "memory")
#define CP_WAITN(n) asm volatile("cp.async.wait_group %0;" :: "n"(n) : "memory")

__device__ __forceinline__ void ldsm4(uint32_t r[4], uint32_t addr) {
    asm volatile("ldmatrix.sync.aligned.m8n8.x4.shared.b16 {%0,%1,%2,%3}, [%4];"
        : "=r"(r[0]), "=r"(r[1]), "=r"(r[2]), "=r"(r[3]) : "r"(addr));
}
__device__ __forceinline__ void mma_f16(float c[4], const uint32_t a[4],
                                        uint32_t b0, uint32_t b1) {
    asm volatile(
        "mma.sync.aligned.m16n8k16.row.col.f32.f16.f16.f32 "
        "{%0,%1,%2,%3}, {%4,%5,%6,%7}, {%8,%9}, {%0,%1,%2,%3};"
        : "+f"(c[0]), "+f"(c[1]), "+f"(c[2]), "+f"(c[3])
        : "r"(a[0]), "r"(a[1]), "r"(a[2]), "r"(a[3]), "r"(b0), "r"(b1));
}

// Swizzled byte offset in a [rows x 32 halves] tile packed as 128B lines
// (2 rows/line). Property: tswz(r,c) == tswz(r,0) ^ (c<<4).
__device__ __forceinline__ uint32_t tswz(int r, int c) {
    uint32_t line = (uint32_t)r >> 1;
    uint32_t pos  = ((((uint32_t)r & 1u) << 2) | (uint32_t)c) ^ (line & 7u);
    return line * 128u + pos * 16u;
}

__device__ __forceinline__ void split2h(float a, float b, uint32_t& hi, uint32_t& lo) {
    __half ha = __float2half_rn(a), hb = __float2half_rn(b);
    float ra = a - __half2float(ha);
    float rb = b - __half2float(hb);
    __half2 H; H.x = ha; H.y = hb;
    __half2 L = __floats2half2_rn(ra, rb);
    hi = *reinterpret_cast<uint32_t*>(&H);
    lo = *reinterpret_cast<uint32_t*>(&L);
}

// ---------------------------------------------------------------------------
// RMSNorm + gamma + fp16 hi/lo split.  x[m][k][d] -> An[k][m][d]
// ---------------------------------------------------------------------------
__global__ __launch_bounds__(256) void rms_split_kernel(
    const float* __restrict__ x, const float* __restrict__ gamma)
{
    int gt = blockIdx.x * blockDim.x + threadIdx.x;
    int row = gt >> 5, lane = gt & 31;
    if (row >= MM * KK) return;
    int m = row / KK, k = row - m * KK;

    const float* xr = x + (size_t)row * DD;
    float4 v[3];
    float s = 0.f;
    #pragma unroll
    for (int i = 0; i < 3; i++) {
        v[i] = *reinterpret_cast<const float4*>(&xr[(lane + i * 32) * 4]);
        s += v[i].x*v[i].x + v[i].y*v[i].y + v[i].z*v[i].z + v[i].w*v[i].w;
    }
    #pragma unroll
    for (int o = 16; o > 0; o >>= 1) s += __shfl_xor_sync(0xffffffffu, s, o);
    s = rsqrtf(s * (1.0f / DD) + 1e-8f);

    const float* gk = gamma + k * DD;
    __half* oh = g_An_hi + ((size_t)k * MM + m) * DD;
    __half* ol = g_An_lo + ((size_t)k * MM + m) * DD;
    #pragma unroll
    for (int i = 0; i < 3; i++) {
        int d = (lane + i * 32) * 4;
        float4 g = *reinterpret_cast<const float4*>(&gk[d]);
        float a0 = v[i].x*s*g.x, a1 = v[i].y*s*g.y, a2 = v[i].z*s*g.z, a3 = v[i].w*s*g.w;
        uint2 H, L;
        split2h(a0, a1, H.x, L.x);
        split2h(a2, a3, H.y, L.y);
        *reinterpret_cast<uint2*>(oh + d) = H;
        *reinterpret_cast<uint2*>(ol + d) = L;
    }
}

// ---------------------------------------------------------------------------
// Per-band transpose + fp16 round. in[k][R][C] -> dst[k][C][R]
// ---------------------------------------------------------------------------
template <int SEL>
__global__ __launch_bounds__(256) void transpose_h_kernel(
    const float* __restrict__ in, int R, int C)
{
    __half* __restrict__ oh = (SEL == 0) ? g_W0T : g_W1T;

    __shared__ float tile[32][33];
    const float* inp = in + (size_t)blockIdx.z * R * C;
    size_t obase = (size_t)blockIdx.z * C * R;
    int r0 = blockIdx.y * 32, c0 = blockIdx.x * 32;
    int tx = threadIdx.x, ty = threadIdx.y;

    #pragma unroll
    for (int j = 0; j < 4; j++)
        tile[ty + 8*j][tx] = inp[(size_t)(r0 + ty + 8*j) * C + c0 + tx];
    __syncthreads();
    #pragma unroll
    for (int j = 0; j < 4; j++) {
        int oc = c0 + ty + 8*j;
        oh[obase + (size_t)oc * R + r0 + tx] = __float2half_rn(tile[tx][ty + 8*j]);
    }
}

// ---------------------------------------------------------------------------
// GEMM1 (mma.sync f16, 2-term): H1[k] = tanh(An[k] @ W0T[k]^T + b0[k])
//   Block 128x128, K-step 32 (12 iters), 3-stage cp.async, ONE sync/iter.
//   8 warps as 4(M)x2(N): warp tile 32x64 (8 LDSM per kc vs 32 MMA).
//   Stage: Ahi 8K | Alo 8K | B 8K = 24KB; 3 stages = 72KB. 2 CTAs/SM.
// ---------------------------------------------------------------------------
#define G1_STAGE 24576
#define G1_SMEM  (3*G1_STAGE)

__global__ __launch_bounds__(256, 2) void gemm1_mma(const float* __restrict__ b0)
{
    extern __shared__ char smem[];
    const uint32_t sb = smem_u32(smem);
    const int t = threadIdx.x, wid = t >> 5, lane = t & 31;
    const int k = blockIdx.z, mb = blockIdx.y * 128, nb = blockIdx.x * 128;
    const int wm = wid & 3, wn = wid >> 2;

    const __half* gA0 = g_An_hi + ((size_t)k * MM  + mb) * DD;
    const __half* gA1 = g_An_lo + ((size_t)k * MM  + mb) * DD;
    const __half* gB  = g_W0T   + ((size_t)k * DFF + nb) * DD;

    // 6 cp chunks/thread: 0..511 Ahi, 512..1023 Alo, 1024..1535 B
    const __half* gbase[6];
    uint32_t sdst[6];
    #pragma unroll
    for (int j = 0; j < 6; j++) {
        int id = t + j * 256;
        int c = id & 3, r = (id >> 2) & 127;
        if (id < 512)        { gbase[j] = gA0 + (size_t)r * DD + c * 8; sdst[j] = tswz(r, c); }
        else if (id < 1024)  { gbase[j] = gA1 + (size_t)r * DD + c * 8; sdst[j] = 8192u  + tswz(r, c); }
        else                 { gbase[j] = gB  + (size_t)r * DD + c * 8; sdst[j] = 16384u + tswz(r, c); }
    }

    const uint32_t laneXor = (uint32_t)((lane >> 4) << 4);
    uint32_t aHiO[2], aLoO[2], bO[4];
    #pragma unroll
    for (int mf = 0; mf < 2; mf++) {
        uint32_t o = tswz(wm * 32 + mf * 16 + (lane & 15), 0) ^ laneXor;
        aHiO[mf] = o; aLoO[mf] = o + 8192;
    }
    #pragma unroll
    for (int g = 0; g < 4; g++)
        bO[g] = (tswz(wn * 64 + g * 16 + (lane & 15), 0) ^ laneXor) + 16384;

    float acc[2][8][4];
    #pragma unroll
    for (int a = 0; a < 2; a++)
        #pragma unroll
        for (int b = 0; b < 8; b++)
            #pragma unroll
            for (int c = 0; c < 4; c++) acc[a][b][c] = 0.f;

    // prologue: stages 0 and 1
    #pragma unroll
    for (int j = 0; j < 6; j++) CP16(sb + sdst[j], gbase[j]);
    CP_COMMIT();
    #pragma unroll
    for (int j = 0; j < 6; j++) CP16(sb + G1_STAGE + sdst[j], gbase[j] + 32);
    CP_COMMIT();

    #pragma unroll 1
    for (int it3 = 0; it3 < 4; ++it3) {
        #pragma unroll
        for (int ph = 0; ph < 3; ph++) {
            const int it = it3 * 3 + ph;
            const uint32_t stb = sb + (uint32_t)(ph * G1_STAGE);
            // stage `it` ready after <=1 pending (steady) / 0 (last iter)
            if (it < 11) CP_WAITN(1); else CP_WAITN(0);
            __syncthreads();   // single barrier: also proves all warps left it-1
            if (it + 2 < 12) {
                const uint32_t stn = sb + (uint32_t)(((ph + 2) % 3) * G1_STAGE);
                const int k0 = (it + 2) * 32;
                #pragma unroll
                for (int j = 0; j < 6; j++) CP16(stn + sdst[j], gbase[j] + k0);
                CP_COMMIT();
            }

            #pragma unroll
            for (int kc = 0; kc < 2; kc++) {
                const uint32_t kx = (uint32_t)(kc << 5);
                uint32_t ah[2][4], al[2][4], b[4][4];
                #pragma unroll
                for (int g = 0; g < 4; g++) ldsm4(b[g], stb + (bO[g] ^ kx));
                #pragma unroll
                for (int mf = 0; mf < 2; mf++) ldsm4(ah[mf], stb + (aHiO[mf] ^ kx));
                #pragma unroll
                for (int mf = 0; mf < 2; mf++)
                    #pragma unroll
                    for (int nf = 0; nf < 8; nf++) {
                        int g = nf >> 1, s = nf & 1;
                        mma_f16(acc[mf][nf], ah[mf], b[g][s], b[g][s + 2]);
                    }
                #pragma unroll
                for (int mf = 0; mf < 2; mf++) ldsm4(al[mf], stb + (aLoO[mf] ^ kx));
                #pragma unroll
                for (int mf = 0; mf < 2; mf++)
                    #pragma unroll
                    for (int nf = 0; nf < 8; nf++) {
                        int g = nf >> 1, s = nf & 1;
                        mma_f16(acc[mf][nf], al[mf], b[g][s], b[g][s + 2]);
                    }
            }
        }
    }

    // epilogue: bias + tanh + fp16 split -> g_H1h/g_H1l
    #pragma unroll
    for (int nf = 0; nf < 8; nf++) {
        int n = nb + wn * 64 + nf * 8 + 2 * (lane & 3);
        float2 bias = *reinterpret_cast<const float2*>(&b0[k * DFF + n]);
        #pragma unroll
        for (int mf = 0; mf < 2; mf++) {
            #pragma unroll
            for (int h = 0; h < 2; h++) {
                int m = mb + wm * 32 + mf * 16 + (lane >> 2) + h * 8;
                float v0 = tanhf(acc[mf][nf][h * 2 + 0] + bias.x);
                float v1 = tanhf(acc[mf][nf][h * 2 + 1] + bias.y);
                uint32_t H, L;
                split2h(v0, v1, H, L);
                size_t off = ((size_t)k * MM + m) * DFF + n;
                *reinterpret_cast<uint32_t*>(g_H1h + off) = H;
                *reinterpret_cast<uint32_t*>(g_H1l + off) = L;
            }
        }
    }
}

// ---------------------------------------------------------------------------
// GEMM2 (mma.sync f16, 2-term): C = H1[k] @ W1T[k]^T + b1; GLU; scatter-add.
//   Block 128x96, K-step 32 (48 iters), 3-stage cp.async, ONE sync/iter.
//   8 warps as 4(M)x2(N): warp tile 32x48. 2 CTAs/SM.
// ---------------------------------------------------------------------------
#define G2_STAGE 22528
#define G2_SMEM  (3*G2_STAGE)

__global__ __launch_bounds__(256, 2) void gemm2_mma(
    const float* __restrict__ b1, float* __restrict__ out)
{
    extern __shared__ char smem[];
    const uint32_t sb = smem_u32(smem);
    const int t = threadIdx.x, wid = t >> 5, lane = t & 31;
    const int k = blockIdx.y, mb = blockIdx.x * 128;
    const int wm = wid & 3, wn = wid >> 2;

    const __half* gA0 = g_H1h + ((size_t)k * MM + mb) * DFF;
    const __half* gA1 = g_H1l + ((size_t)k * MM + mb) * DFF;
    const __half* gB  = g_W1T + (size_t)k * NOUT * DFF;

    // 6 cp chunks/thread (guarded): 0..511 Ahi, 512..1023 Alo, 1024..1407 B
    const __half* gbase[6];
    uint32_t sdst[6];
    #pragma unroll
    for (int j = 0; j < 6; j++) {
        int id = t + j * 256;
        if (id >= 1408) { gbase[j] = nullptr; sdst[j] = 0; continue; }
        int c = id & 3, r = (id >> 2) & 127;
        if (id < 512)        { gbase[j] = gA0 + (size_t)r * DFF + c * 8; sdst[j] = tswz(r, c); }
        else if (id < 1024)  { gbase[j] = gA1 + (size_t)r * DFF + c * 8; sdst[j] = 8192u  + tswz(r, c); }
        else                 { int rb = (id - 1024) >> 2;
                               gbase[j] = gB + (size_t)rb * DFF + c * 8;
                               sdst[j]  = 16384u + tswz(rb, c); }
    }

    const uint32_t laneXor = (uint32_t)((lane >> 4) << 4);
    uint32_t aHiO[2], aLoO[2], bO[3];
    #pragma unroll
    for (int mf = 0; mf < 2; mf++) {
        uint32_t o = tswz(wm * 32 + mf * 16 + (lane & 15), 0) ^ laneXor;
        aHiO[mf] = o; aLoO[mf] = o + 8192;
    }
    #pragma unroll
    for (int g = 0; g < 3; g++)
        bO[g] = (tswz(wn * 48 + g * 16 + (lane & 15), 0) ^ laneXor) + 16384;

    float acc[2][6][4];
    #pragma unroll
    for (int a = 0; a < 2; a++)
        #pragma unroll
        for (int b = 0; b < 6; b++)
            #pragma unroll
            for (int c = 0; c < 4; c++) acc[a][b][c] = 0.f;

    #pragma unroll
    for (int j = 0; j < 6; j++) if (gbase[j]) CP16(sb + sdst[j], gbase[j]);
    CP_COMMIT();
    #pragma unroll
    for (int j = 0; j < 6; j++) if (gbase[j]) CP16(sb + G2_STAGE + sdst[j], gbase[j] + 32);
    CP_COMMIT();

    #pragma unroll 1
    for (int it3 = 0; it3 < 16; ++it3) {
        #pragma unroll
        for (int ph = 0; ph < 3; ph++) {
            const int it = it3 * 3 + ph;
            const uint32_t stb = sb + (uint32_t)(ph * G2_STAGE);
            if (it < 47) CP_WAITN(1); else CP_WAITN(0);
            __syncthreads();
            if (it + 2 < 48) {
                const uint32_t stn = sb + (uint32_t)(((ph + 2) % 3) * G2_STAGE);
                const int k0 = (it + 2) * 32;
                #pragma unroll
                for (int j = 0; j < 6; j++)
                    if (gbase[j]) CP16(stn + sdst[j], gbase[j] + k0);
                CP_COMMIT();
            }

            #pragma unroll
            for (int kc = 0; kc < 2; kc++) {
                const uint32_t kx = (uint32_t)(kc << 5);
                uint32_t ah[2][4], al[2][4], b[3][4];
                #pragma unroll
                for (int g = 0; g < 3; g++) ldsm4(b[g], stb + (bO[g] ^ kx));
                #pragma unroll
                for (int mf = 0; mf < 2; mf++) ldsm4(ah[mf], stb + (aHiO[mf] ^ kx));
                #pragma unroll
                for (int mf = 0; mf < 2; mf++)
                    #pragma unroll
                    for (int nf = 0; nf < 6; nf++) {
                        int g = nf >> 1, s = nf & 1;
                        mma_f16(acc[mf][nf], ah[mf], b[g][s], b[g][s + 2]);
                    }
                #pragma unroll
                for (int mf = 0; mf < 2; mf++) ldsm4(al[mf], stb + (aLoO[mf] ^ kx));
                #pragma unroll
                for (int mf = 0; mf < 2; mf++)
                    #pragma unroll
                    for (int nf = 0; nf < 6; nf++) {
                        int g = nf >> 1, s = nf & 1;
                        mma_f16(acc[mf][nf], al[mf], b[g][s], b[g][s + 2]);
                    }
            }
        }
    }
    __syncthreads();   // all reads done before epilogue reuses smem

    // epilogue: stage C in smem, then GLU + scatter-add
    float* Cs = reinterpret_cast<float*>(smem);   // 128 x 100 floats
    #pragma unroll
    for (int nf = 0; nf < 6; nf++) {
        int n = wn * 48 + nf * 8 + 2 * (lane & 3);
        #pragma unroll
        for (int mf = 0; mf < 2; mf++) {
            #pragma unroll
            for (int h = 0; h < 2; h++) {
                int m = wm * 32 + mf * 16 + (lane >> 2) + h * 8;
                float2 v;
                v.x = acc[mf][nf][h * 2 + 0];
                v.y = acc[mf][nf][h * 2 + 1];
                *reinterpret_cast<float2*>(&Cs[m * 100 + n]) = v;
            }
        }
    }
    __syncthreads();

    {
        int m = t >> 1;
        int j0 = (t & 1) * 24;
        int gm = mb + m, bidx = gm >> 9, tidx = gm & 511;
        const float* bA = b1 + k * NOUT;
        #pragma unroll
        for (int jj = 0; jj < 24; jj++) {
            int j = j0 + jj;
            float a = Cs[m * 100 + j]      + bA[j];
            float g = Cs[m * 100 + j + 48] + bA[j + 48];
            float ch = a * (1.0f / (1.0f + __expf(-g)));
            int p = k * 32 + j;
            int oi = ((bidx * 2 + (p & 1)) * TT + tidx) * FREQ + (p >> 1);
            atomicAdd(&out[oi], ch);
        }
    }
}

// ---------------------------------------------------------------------------
extern "C" void kernel_launch(void* const* d_in, const int* in_sizes, int n_in,
                              void* d_out, int out_size)
{
    (void)in_sizes; (void)n_in;
    const float* x     = (const float*)d_in[0];
    const float* gamma = (const float*)d_in[1];
    const float* W0    = (const float*)d_in[2];
    const float* b0    = (const float*)d_in[3];
    const float* W1    = (const float*)d_in[4];
    const float* b1    = (const float*)d_in[5];
    float*       out   = (float*)d_out;

    cudaFuncSetAttribute(gemm1_mma, cudaFuncAttributeMaxDynamicSharedMemorySize, G1_SMEM);
    cudaFuncSetAttribute(gemm2_mma, cudaFuncAttributeMaxDynamicSharedMemorySize, G2_SMEM);

    cudaMemsetAsync(out, 0, (size_t)out_size * sizeof(float));

    {
        dim3 b(32, 8);
        dim3 g0(DFF / 32, DD / 32, KK);
        transpose_h_kernel<0><<<g0, b>>>(W0, DD, DFF);
        dim3 g1(NOUT / 32, DFF / 32, KK);
        transpose_h_kernel<1><<<g1, b>>>(W1, DFF, NOUT);
    }

    rms_split_kernel<<<(MM * KK * 32 + 255) / 256, 256>>>(x, gamma);

    dim3 g1(DFF / 128, MM / 128, KK);      // (12, 16, 63)
    gemm1_mma<<<g1, 256, G1_SMEM>>>(b0);

    dim3 g2(MM / 128, KK);                 // (16, 63)
    gemm2_mma<<<g2, 256, G2_SMEM>>>(b1, out);
}

// round 9
// speedup vs baseline: 2.4361x; 1.7643x over previous
#include <cuda_runtime.h>
#include <cuda_fp16.h>
#include <cstdint>

// Problem constants
#define BB   4
#define TT   512
#define KK   63
#define DD   384
#define DFF  1536
#define MM   (BB*TT)          // 2048
#define NOUT 96
#define FREQ 1016

// ---------------------------------------------------------------------------
// Scratch (device globals; ONLY referenced from device code — see R3 bug).
// Single-pass fp16 everywhere (error budget: ~4.5e-4 vs 1e-3 gate).
// ---------------------------------------------------------------------------
__device__ __align__(16) __half g_An [(size_t)KK * MM * DD];
__device__ __align__(16) __half g_W0T[(size_t)KK * DFF * DD];
__device__ __align__(16) __half g_W1T[(size_t)KK * NOUT * DFF];
__device__ __align__(16) __half g_H1 [(size_t)KK * MM * DFF];

// ---------------------------------------------------------------------------
// Portable PTX helpers (plain sm_103)
// ---------------------------------------------------------------------------
__device__ __forceinline__ uint32_t smem_u32(const void* p) {
    uint32_t a;
    asm("{ .reg .u64 t; cvta.to.shared.u64 t, %1; cvt.u32.u64 %0, t; }"
        : "=r"(a) : "l"(p));
    return a;
}
#define CP16(dst, src) \
    asm volatile("cp.async.cg.shared.global [%0], [%1], 16;" \
                 :: "r"(dst), "l"(src) : "memory")
#define CP_COMMIT() asm volatile("cp.async.commit_group;" ::: "memory")
#define CP_WAITN(n) asm volatile("cp.async.wait_group %0;" :: "n"(n) : "memory")

__device__ __forceinline__ void ldsm4(uint32_t r[4], uint32_t addr) {
    asm volatile("ldmatrix.sync.aligned.m8n8.x4.shared.b16 {%0,%1,%2,%3}, [%4];"
        : "=r"(r[0]), "=r"(r[1]), "=r"(r[2]), "=r"(r[3]) : "r"(addr));
}
__device__ __forceinline__ void mma_f16(float c[4], const uint32_t a[4],
                                        uint32_t b0, uint32_t b1) {
    asm volatile(
        "mma.sync.aligned.m16n8k16.row.col.f32.f16.f16.f32 "
        "{%0,%1,%2,%3}, {%4,%5,%6,%7}, {%8,%9}, {%0,%1,%2,%3};"
        : "+f"(c[0]), "+f"(c[1]), "+f"(c[2]), "+f"(c[3])
        : "r"(a[0]), "r"(a[1]), "r"(a[2]), "r"(a[3]), "r"(b0), "r"(b1));
}

// Swizzled byte offset in a [rows x 32 halves] tile packed as 128B lines
// (2 rows/line). Property: tswz(r,c) == tswz(r,0) ^ (c<<4).
__device__ __forceinline__ uint32_t tswz(int r, int c) {
    uint32_t line = (uint32_t)r >> 1;
    uint32_t pos  = ((((uint32_t)r & 1u) << 2) | (uint32_t)c) ^ (line & 7u);
    return line * 128u + pos * 16u;
}

// ---------------------------------------------------------------------------
// RMSNorm + gamma -> fp16.  x[m][k][d] -> An[k][m][d]
// ---------------------------------------------------------------------------
__global__ __launch_bounds__(256) void rms_kernel(
    const float* __restrict__ x, const float* __restrict__ gamma)
{
    int gt = blockIdx.x * blockDim.x + threadIdx.x;
    int row = gt >> 5, lane = gt & 31;
    if (row >= MM * KK) return;
    int m = row / KK, k = row - m * KK;

    const float* xr = x + (size_t)row * DD;
    float4 v[3];
    float s = 0.f;
    #pragma unroll
    for (int i = 0; i < 3; i++) {
        v[i] = *reinterpret_cast<const float4*>(&xr[(lane + i * 32) * 4]);
        s += v[i].x*v[i].x + v[i].y*v[i].y + v[i].z*v[i].z + v[i].w*v[i].w;
    }
    #pragma unroll
    for (int o = 16; o > 0; o >>= 1) s += __shfl_xor_sync(0xffffffffu, s, o);
    s = rsqrtf(s * (1.0f / DD) + 1e-8f);

    const float* gk = gamma + k * DD;
    __half* oh = g_An + ((size_t)k * MM + m) * DD;
    #pragma unroll
    for (int i = 0; i < 3; i++) {
        int d = (lane + i * 32) * 4;
        float4 g = *reinterpret_cast<const float4*>(&gk[d]);
        __half2 h0 = __floats2half2_rn(v[i].x*s*g.x, v[i].y*s*g.y);
        __half2 h1 = __floats2half2_rn(v[i].z*s*g.z, v[i].w*s*g.w);
        uint2 H;
        H.x = *reinterpret_cast<uint32_t*>(&h0);
        H.y = *reinterpret_cast<uint32_t*>(&h1);
        *reinterpret_cast<uint2*>(oh + d) = H;
    }
}

// ---------------------------------------------------------------------------
// Per-band transpose + fp16 round. in[k][R][C] -> dst[k][C][R]
// ---------------------------------------------------------------------------
template <int SEL>
__global__ __launch_bounds__(256) void transpose_h_kernel(
    const float* __restrict__ in, int R, int C)
{
    __half* __restrict__ oh = (SEL == 0) ? g_W0T : g_W1T;

    __shared__ float tile[32][33];
    const float* inp = in + (size_t)blockIdx.z * R * C;
    size_t obase = (size_t)blockIdx.z * C * R;
    int r0 = blockIdx.y * 32, c0 = blockIdx.x * 32;
    int tx = threadIdx.x, ty = threadIdx.y;

    #pragma unroll
    for (int j = 0; j < 4; j++)
        tile[ty + 8*j][tx] = inp[(size_t)(r0 + ty + 8*j) * C + c0 + tx];
    __syncthreads();
    #pragma unroll
    for (int j = 0; j < 4; j++) {
        int oc = c0 + ty + 8*j;
        oh[obase + (size_t)oc * R + r0 + tx] = __float2half_rn(tile[tx][ty + 8*j]);
    }
}

// ---------------------------------------------------------------------------
// GEMM1 (mma.sync f16, 1-pass): H1[k] = tanh(An[k] @ W0T[k]^T + b0[k])
//   Block 128x128, K-step 32 (12 iters), 4-stage cp.async, ONE sync/iter.
//   8 warps as 4(M)x2(N): warp tile 32x64. Stage: A 8K | B 8K = 16KB x4 = 64KB.
//   2 CTAs/SM.
// ---------------------------------------------------------------------------
#define G1_STAGE 16384
#define G1_SMEM  (4*G1_STAGE)

__global__ __launch_bounds__(256, 2) void gemm1_mma(const float* __restrict__ b0)
{
    extern __shared__ char smem[];
    const uint32_t sb = smem_u32(smem);
    const int t = threadIdx.x, wid = t >> 5, lane = t & 31;
    const int k = blockIdx.z, mb = blockIdx.y * 128, nb = blockIdx.x * 128;
    const int wm = wid & 3, wn = wid >> 2;

    const __half* gA = g_An  + ((size_t)k * MM  + mb) * DD;
    const __half* gB = g_W0T + ((size_t)k * DFF + nb) * DD;

    // 4 cp chunks/thread: ids 0..511 A, 512..1023 B
    const __half* gbase[4];
    uint32_t sdst[4];
    #pragma unroll
    for (int j = 0; j < 4; j++) {
        int id = t + j * 256;
        int c = id & 3, r = (id >> 2) & 127;
        if (id < 512) { gbase[j] = gA + (size_t)r * DD + c * 8; sdst[j] = tswz(r, c); }
        else          { gbase[j] = gB + (size_t)r * DD + c * 8; sdst[j] = 8192u + tswz(r, c); }
    }

    const uint32_t laneXor = (uint32_t)((lane >> 4) << 4);
    uint32_t aO[2], bO[4];
    #pragma unroll
    for (int mf = 0; mf < 2; mf++)
        aO[mf] = tswz(wm * 32 + mf * 16 + (lane & 15), 0) ^ laneXor;
    #pragma unroll
    for (int g = 0; g < 4; g++)
        bO[g] = (tswz(wn * 64 + g * 16 + (lane & 15), 0) ^ laneXor) + 8192;

    float acc[2][8][4];
    #pragma unroll
    for (int a = 0; a < 2; a++)
        #pragma unroll
        for (int b = 0; b < 8; b++)
            #pragma unroll
            for (int c = 0; c < 4; c++) acc[a][b][c] = 0.f;

    // prologue: stages 0..2
    #pragma unroll
    for (int st = 0; st < 3; st++) {
        #pragma unroll
        for (int j = 0; j < 4; j++)
            CP16(sb + st * G1_STAGE + sdst[j], gbase[j] + st * 32);
        CP_COMMIT();
    }

    #pragma unroll 1
    for (int it4 = 0; it4 < 3; ++it4) {
        #pragma unroll
        for (int ph = 0; ph < 4; ph++) {
            const int it = it4 * 4 + ph;
            const uint32_t stb = sb + (uint32_t)(ph * G1_STAGE);
            if (it < 10) CP_WAITN(2);
            else if (it == 10) CP_WAITN(1);
            else CP_WAITN(0);
            __syncthreads();   // also proves all warps finished iter it-1 reads
            if (it + 3 < 12) {
                const uint32_t stn = sb + (uint32_t)(((ph + 3) & 3) * G1_STAGE);
                const int k0 = (it + 3) * 32;
                #pragma unroll
                for (int j = 0; j < 4; j++) CP16(stn + sdst[j], gbase[j] + k0);
                CP_COMMIT();
            }

            #pragma unroll
            for (int kc = 0; kc < 2; kc++) {
                const uint32_t kx = (uint32_t)(kc << 5);
                uint32_t a[2][4], b[4][4];
                #pragma unroll
                for (int g = 0; g < 4; g++) ldsm4(b[g], stb + (bO[g] ^ kx));
                #pragma unroll
                for (int mf = 0; mf < 2; mf++) ldsm4(a[mf], stb + (aO[mf] ^ kx));
                #pragma unroll
                for (int mf = 0; mf < 2; mf++)
                    #pragma unroll
                    for (int nf = 0; nf < 8; nf++) {
                        int g = nf >> 1, s = nf & 1;
                        mma_f16(acc[mf][nf], a[mf], b[g][s], b[g][s + 2]);
                    }
            }
        }
    }

    // epilogue: bias + tanh -> g_H1 (fp16)
    #pragma unroll
    for (int nf = 0; nf < 8; nf++) {
        int n = nb + wn * 64 + nf * 8 + 2 * (lane & 3);
        float2 bias = *reinterpret_cast<const float2*>(&b0[k * DFF + n]);
        #pragma unroll
        for (int mf = 0; mf < 2; mf++) {
            #pragma unroll
            for (int h = 0; h < 2; h++) {
                int m = mb + wm * 32 + mf * 16 + (lane >> 2) + h * 8;
                float v0 = tanhf(acc[mf][nf][h * 2 + 0] + bias.x);
                float v1 = tanhf(acc[mf][nf][h * 2 + 1] + bias.y);
                __half2 hv = __floats2half2_rn(v0, v1);
                size_t off = ((size_t)k * MM + m) * DFF + n;
                *reinterpret_cast<uint32_t*>(g_H1 + off) =
                    *reinterpret_cast<uint32_t*>(&hv);
            }
        }
    }
}

// ---------------------------------------------------------------------------
// GEMM2 (mma.sync f16, 1-pass): C = H1[k] @ W1T[k]^T + b1; GLU; scatter-add.
//   Block 128x96, K-step 32 (48 iters), 4-stage cp.async, ONE sync/iter.
//   8 warps as 4(M)x2(N): warp tile 32x48. Stage: A 8K | B 6K = 14KB x4.
//   2 CTAs/SM. Epilogue Cs = 128x100 f32 = 50KB (fits in 56KB smem).
// ---------------------------------------------------------------------------
#define G2_STAGE 14336
#define G2_SMEM  (4*G2_STAGE)

__global__ __launch_bounds__(256, 2) void gemm2_mma(
    const float* __restrict__ b1, float* __restrict__ out)
{
    extern __shared__ char smem[];
    const uint32_t sb = smem_u32(smem);
    const int t = threadIdx.x, wid = t >> 5, lane = t & 31;
    const int k = blockIdx.y, mb = blockIdx.x * 128;
    const int wm = wid & 3, wn = wid >> 2;

    const __half* gA = g_H1  + ((size_t)k * MM + mb) * DFF;
    const __half* gB = g_W1T + (size_t)k * NOUT * DFF;

    // 4 cp chunks/thread (guarded): ids 0..511 A, 512..895 B
    const __half* gbase[4];
    uint32_t sdst[4];
    #pragma unroll
    for (int j = 0; j < 4; j++) {
        int id = t + j * 256;
        if (id >= 896) { gbase[j] = nullptr; sdst[j] = 0; continue; }
        int c = id & 3, r = (id >> 2) & 127;
        if (id < 512) { gbase[j] = gA + (size_t)r * DFF + c * 8; sdst[j] = tswz(r, c); }
        else          { int rb = (id - 512) >> 2;
                        gbase[j] = gB + (size_t)rb * DFF + c * 8;
                        sdst[j]  = 8192u + tswz(rb, c); }
    }

    const uint32_t laneXor = (uint32_t)((lane >> 4) << 4);
    uint32_t aO[2], bO[3];
    #pragma unroll
    for (int mf = 0; mf < 2; mf++)
        aO[mf] = tswz(wm * 32 + mf * 16 + (lane & 15), 0) ^ laneXor;
    #pragma unroll
    for (int g = 0; g < 3; g++)
        bO[g] = (tswz(wn * 48 + g * 16 + (lane & 15), 0) ^ laneXor) + 8192;

    float acc[2][6][4];
    #pragma unroll
    for (int a = 0; a < 2; a++)
        #pragma unroll
        for (int b = 0; b < 6; b++)
            #pragma unroll
            for (int c = 0; c < 4; c++) acc[a][b][c] = 0.f;

    #pragma unroll
    for (int st = 0; st < 3; st++) {
        #pragma unroll
        for (int j = 0; j < 4; j++)
            if (gbase[j]) CP16(sb + st * G2_STAGE + sdst[j], gbase[j] + st * 32);
        CP_COMMIT();
    }

    #pragma unroll 1
    for (int it4 = 0; it4 < 12; ++it4) {
        #pragma unroll
        for (int ph = 0; ph < 4; ph++) {
            const int it = it4 * 4 + ph;
            const uint32_t stb = sb + (uint32_t)(ph * G2_STAGE);
            if (it < 46) CP_WAITN(2);
            else if (it == 46) CP_WAITN(1);
            else CP_WAITN(0);
            __syncthreads();
            if (it + 3 < 48) {
                const uint32_t stn = sb + (uint32_t)(((ph + 3) & 3) * G2_STAGE);
                const int k0 = (it + 3) * 32;
                #pragma unroll
                for (int j = 0; j < 4; j++)
                    if (gbase[j]) CP16(stn + sdst[j], gbase[j] + k0);
                CP_COMMIT();
            }

            #pragma unroll
            for (int kc = 0; kc < 2; kc++) {
                const uint32_t kx = (uint32_t)(kc << 5);
                uint32_t a[2][4], b[3][4];
                #pragma unroll
                for (int g = 0; g < 3; g++) ldsm4(b[g], stb + (bO[g] ^ kx));
                #pragma unroll
                for (int mf = 0; mf < 2; mf++) ldsm4(a[mf], stb + (aO[mf] ^ kx));
                #pragma unroll
                for (int mf = 0; mf < 2; mf++)
                    #pragma unroll
                    for (int nf = 0; nf < 6; nf++) {
                        int g = nf >> 1, s = nf & 1;
                        mma_f16(acc[mf][nf], a[mf], b[g][s], b[g][s + 2]);
                    }
            }
        }
    }
    __syncthreads();   // all smem reads done before epilogue reuses smem

    // epilogue: stage C in smem, then GLU + scatter-add
    float* Cs = reinterpret_cast<float*>(smem);   // 128 x 100 floats
    #pragma unroll
    for (int nf = 0; nf < 6; nf++) {
        int n = wn * 48 + nf * 8 + 2 * (lane & 3);
        #pragma unroll
        for (int mf = 0; mf < 2; mf++) {
            #pragma unroll
            for (int h = 0; h < 2; h++) {
                int m = wm * 32 + mf * 16 + (lane >> 2) + h * 8;
                float2 v;
                v.x = acc[mf][nf][h * 2 + 0];
                v.y = acc[mf][nf][h * 2 + 1];
                *reinterpret_cast<float2*>(&Cs[m * 100 + n]) = v;
            }
        }
    }
    __syncthreads();

    {
        int m = t >> 1;
        int j0 = (t & 1) * 24;
        int gm = mb + m, bidx = gm >> 9, tidx = gm & 511;
        const float* bA = b1 + k * NOUT;
        #pragma unroll
        for (int jj = 0; jj < 24; jj++) {
            int j = j0 + jj;
            float a = Cs[m * 100 + j]      + bA[j];
            float g = Cs[m * 100 + j + 48] + bA[j + 48];
            float ch = a * (1.0f / (1.0f + __expf(-g)));
            int p = k * 32 + j;
            int oi = ((bidx * 2 + (p & 1)) * TT + tidx) * FREQ + (p >> 1);
            atomicAdd(&out[oi], ch);
        }
    }
}

// ---------------------------------------------------------------------------
extern "C" void kernel_launch(void* const* d_in, const int* in_sizes, int n_in,
                              void* d_out, int out_size)
{
    (void)in_sizes; (void)n_in;
    const float* x     = (const float*)d_in[0];
    const float* gamma = (const float*)d_in[1];
    const float* W0    = (const float*)d_in[2];
    const float* b0    = (const float*)d_in[3];
    const float* W1    = (const float*)d_in[4];
    const float* b1    = (const float*)d_in[5];
    float*       out   = (float*)d_out;

    cudaFuncSetAttribute(gemm1_mma, cudaFuncAttributeMaxDynamicSharedMemorySize, G1_SMEM);
    cudaFuncSetAttribute(gemm2_mma, cudaFuncAttributeMaxDynamicSharedMemorySize, G2_SMEM);

    cudaMemsetAsync(out, 0, (size_t)out_size * sizeof(float));

    {
        dim3 b(32, 8);
        dim3 g0(DFF / 32, DD / 32, KK);
        transpose_h_kernel<0><<<g0, b>>>(W0, DD, DFF);
        dim3 g1(NOUT / 32, DFF / 32, KK);
        transpose_h_kernel<1><<<g1, b>>>(W1, DFF, NOUT);
    }

    rms_kernel<<<(MM * KK * 32 + 255) / 256, 256>>>(x, gamma);

    dim3 g1(DFF / 128, MM / 128, KK);      // (12, 16, 63)
    gemm1_mma<<<g1, 256, G1_SMEM>>>(b0);

    dim3 g2(MM / 128, KK);                 // (16, 63)
    gemm2_mma<<<g2, 256, G2_SMEM>>>(b1, out);
}